// round 13
// baseline (speedup 1.0000x reference)
#include <cuda_runtime.h>
#include <cuda_fp16.h>
#include <cstdint>

// ---------------------------------------------------------------------------
// Problem constants
// ---------------------------------------------------------------------------
#define NSAMP 4096
#define DIM   1024     // IN == HID == DIM_T
#define LAYERS 4
#define GROWS (LAYERS*4*DIM)       // 16384 stacked gate rows
#define NSTEP (NSAMP*LAYERS)       // 16384 sequential steps
#define NCTA  147                  // scan CTAs; CTA k owns h[7k .. 7k+7)

// ---------------------------------------------------------------------------
// Scratch (static device globals; no runtime allocation)
// ---------------------------------------------------------------------------
__device__ float g_PE [(size_t)NSAMP*DIM];
__device__ float g_T1 [(size_t)NSAMP*DIM];
__device__ float g_EMB[(size_t)NSAMP*DIM];
__device__ float g_XP [(size_t)NSAMP*DIM];
__device__ float g_R  [(size_t)GROWS*NSAMP];   // 256 MB: R[row, i]
__device__ float g_H  [(size_t)NSAMP*DIM];
__device__ float g_BS [GROWS];
__device__ __half g_WihH[(size_t)GROWS*DIM];   // 32 MB fp16 Wih
__device__ __half g_XPH [(size_t)NSAMP*DIM];   // 8 MB fp16 XP
// h exchange: ONE 16B slot per CTA = {7 x fp16 h, 16-bit tag}, double-buffered
// by step parity: buffer b holds steps with (g&1)==b.
__device__ uint4 g_hx[2*NCTA];

// ---------------------------------------------------------------------------
// 16B GPU-scope vector ld/st (performed at L2; no SYS/C2C coherence cost)
// ---------------------------------------------------------------------------
__device__ __forceinline__ uint4 ldv4(const uint4* p) {
    uint4 v;
    asm volatile("ld.relaxed.gpu.global.v4.u32 {%0,%1,%2,%3}, [%4];"
                 : "=r"(v.x), "=r"(v.y), "=r"(v.z), "=r"(v.w) : "l"(p) : "memory");
    return v;
}
__device__ __forceinline__ void stv4(uint4* p, uint4 v) {
    asm volatile("st.relaxed.gpu.global.v4.u32 [%0], {%1,%2,%3,%4};"
                 :: "l"(p), "r"(v.x), "r"(v.y), "r"(v.z), "r"(v.w) : "memory");
}

// ---------------------------------------------------------------------------
// Small prologue kernels
// ---------------------------------------------------------------------------
__global__ void pe_kernel(const int* __restrict__ ts, float* __restrict__ PE) {
    int i = blockIdx.x;
    float t = (float)ts[i];
    for (int d = threadIdx.x; d < DIM/2; d += blockDim.x) {
        float f = expf((float)d * (-9.210340371976184f / (float)(DIM/2 - 1)));
        float a = t * f;
        PE[(size_t)i*DIM + d]          = sinf(a);
        PE[(size_t)i*DIM + DIM/2 + d]  = cosf(a);
    }
}

__global__ void bias_kernel(const float* __restrict__ bih, const float* __restrict__ bhh,
                            float* __restrict__ out) {
    int idx = blockIdx.x*blockDim.x + threadIdx.x;
    if (idx < GROWS) out[idx] = bih[idx] + bhh[idx];
}

__global__ void reset_kernel() {
    int idx = blockIdx.x*blockDim.x + threadIdx.x;
    if (idx < 2*NCTA) g_hx[idx] = make_uint4(0u, 0u, 0u, 0u);  // tag 0, h = 0
}

__global__ void conv_fp16_kernel(const float* __restrict__ src,
                                 __half* __restrict__ dst, int n4) {
    int i = blockIdx.x*blockDim.x + threadIdx.x;
    if (i < n4) {
        float4 v = *(const float4*)&src[(size_t)i*4];
        __half o[4];
        o[0] = __float2half_rn(v.x);
        o[1] = __float2half_rn(v.y);
        o[2] = __float2half_rn(v.z);
        o[3] = __float2half_rn(v.w);
        *(uint2*)&dst[(size_t)i*4] = *(uint2*)o;
    }
}

// ---------------------------------------------------------------------------
// Generic NT GEMM (fp32 SIMT) for the small GEMMs: C = A@B^T (+bias/add/silu)
// ---------------------------------------------------------------------------
__global__ __launch_bounds__(256, 2)
void gemm_nt(const float* __restrict__ A, const float* __restrict__ B,
             float* __restrict__ C, int M, int N, int K,
             const float* __restrict__ biasM, const float* __restrict__ biasN,
             const float* __restrict__ addMN, int do_silu)
{
    const int BM = 128, BK = 16;
    __shared__ float As[2][16][128+8];
    __shared__ float Bs[2][16][128+8];

    const int tid = threadIdx.x;
    const int m0 = blockIdx.y * BM, n0 = blockIdx.x * BM;
    const int tx = tid & 15, ty = tid >> 4;

    float4 aF[2], bF[2];

    #pragma unroll
    for (int i = 0; i < 2; i++) {
        int f = tid + i*256;
        int row = f >> 2, c4 = (f & 3) * 4;
        aF[i] = *(const float4*)&A[(size_t)(m0+row)*K + c4];
        bF[i] = *(const float4*)&B[(size_t)(n0+row)*K + c4];
    }
    #pragma unroll
    for (int i = 0; i < 2; i++) {
        int f = tid + i*256;
        int row = f >> 2, c4 = (f & 3) * 4;
        As[0][c4+0][row] = aF[i].x; As[0][c4+1][row] = aF[i].y;
        As[0][c4+2][row] = aF[i].z; As[0][c4+3][row] = aF[i].w;
        Bs[0][c4+0][row] = bF[i].x; Bs[0][c4+1][row] = bF[i].y;
        Bs[0][c4+2][row] = bF[i].z; Bs[0][c4+3][row] = bF[i].w;
    }
    __syncthreads();

    float acc[8][8];
    #pragma unroll
    for (int i = 0; i < 8; i++)
        #pragma unroll
        for (int j = 0; j < 8; j++) acc[i][j] = 0.f;

    const int nk = K / BK;
    for (int kt = 0; kt < nk; kt++) {
        const int cur = kt & 1;
        if (kt + 1 < nk) {
            int k0 = (kt+1)*BK;
            #pragma unroll
            for (int i = 0; i < 2; i++) {
                int f = tid + i*256;
                int row = f >> 2, c4 = (f & 3) * 4;
                aF[i] = *(const float4*)&A[(size_t)(m0+row)*K + k0 + c4];
                bF[i] = *(const float4*)&B[(size_t)(n0+row)*K + k0 + c4];
            }
        }
        #pragma unroll
        for (int k = 0; k < BK; k++) {
            float a[8], b[8];
            *(float4*)&a[0] = *(const float4*)&As[cur][k][ty*8];
            *(float4*)&a[4] = *(const float4*)&As[cur][k][ty*8+4];
            *(float4*)&b[0] = *(const float4*)&Bs[cur][k][tx*8];
            *(float4*)&b[4] = *(const float4*)&Bs[cur][k][tx*8+4];
            #pragma unroll
            for (int i = 0; i < 8; i++)
                #pragma unroll
                for (int j = 0; j < 8; j++)
                    acc[i][j] += a[i] * b[j];
        }
        if (kt + 1 < nk) {
            const int nxt = cur ^ 1;
            #pragma unroll
            for (int i = 0; i < 2; i++) {
                int f = tid + i*256;
                int row = f >> 2, c4 = (f & 3) * 4;
                As[nxt][c4+0][row] = aF[i].x; As[nxt][c4+1][row] = aF[i].y;
                As[nxt][c4+2][row] = aF[i].z; As[nxt][c4+3][row] = aF[i].w;
                Bs[nxt][c4+0][row] = bF[i].x; Bs[nxt][c4+1][row] = bF[i].y;
                Bs[nxt][c4+2][row] = bF[i].z; Bs[nxt][c4+3][row] = bF[i].w;
            }
            __syncthreads();
        }
    }

    #pragma unroll
    for (int i = 0; i < 8; i++) {
        int m = m0 + ty*8 + i;
        float bm = biasM ? biasM[m] : 0.f;
        #pragma unroll
        for (int j = 0; j < 8; j++) {
            int n = n0 + tx*8 + j;
            float v = acc[i][j] + bm;
            if (biasN) v += biasN[n];
            if (addMN) v += addMN[(size_t)m*N + n];
            if (do_silu) v = v / (1.f + __expf(-v));
            C[(size_t)m*N + n] = v;
        }
    }
}

// ---------------------------------------------------------------------------
// fp16 tensor-core GEMM for R:  C[16384,4096] = A[16384,1024] @ B[4096,1024]^T + biasM
// NT GEMM, both operands k-major -> BOTH sides use NON-TRANS ldmatrix.
// ---------------------------------------------------------------------------
#define RLD 40    // padded halves per SMEM row

__global__ __launch_bounds__(256, 2)
void gemm_r_fp16(const __half* __restrict__ A,
                 const __half* __restrict__ B,
                 const float* __restrict__ biasM,
                 float* __restrict__ C)
{
    __shared__ __align__(16) unsigned short As[2][128*RLD];
    __shared__ __align__(16) unsigned short Bs[2][64*RLD];

    const int tid = threadIdx.x;
    const int m0 = blockIdx.y * 128;
    const int n0 = blockIdx.x * 64;
    const int w  = tid >> 5, lane = tid & 31;
    const int wm = (w & 3) * 32;
    const int wn = (w >> 2) * 32;

    const int ar0 = tid >> 2,          ac = (tid & 3) * 8;
    const int ar1 = (tid >> 2) + 64;
    const int br  = tid >> 2;

    const __half* Ag = A + (size_t)m0*DIM;
    const __half* Bg = B + (size_t)n0*DIM;

    uint4 aR0 = *(const uint4*)(Ag + (size_t)ar0*DIM + ac);
    uint4 aR1 = *(const uint4*)(Ag + (size_t)ar1*DIM + ac);
    uint4 bR  = *(const uint4*)(Bg + (size_t)br *DIM + ac);
    *(uint4*)&As[0][ar0*RLD + ac] = aR0;
    *(uint4*)&As[0][ar1*RLD + ac] = aR1;
    *(uint4*)&Bs[0][br *RLD + ac] = bR;
    __syncthreads();

    float acc[2][4][4];
    #pragma unroll
    for (int tm = 0; tm < 2; tm++)
        #pragma unroll
        for (int tn = 0; tn < 4; tn++)
            #pragma unroll
            for (int e = 0; e < 4; e++) acc[tm][tn][e] = 0.f;

    const uint32_t aoff = ((uint32_t)(wm + (lane & 15)) * RLD + (lane >> 4) * 8) * 2;
    const uint32_t boff = ((uint32_t)(wn + (lane & 7))  * RLD + ((lane >> 3) & 1) * 8) * 2;
    const uint32_t aSm0 = (uint32_t)__cvta_generic_to_shared(&As[0][0]);
    const uint32_t bSm0 = (uint32_t)__cvta_generic_to_shared(&Bs[0][0]);
    const uint32_t aBufStride = 128*RLD*2;
    const uint32_t bBufStride = 64*RLD*2;

    const int NKT = DIM / 32;
    for (int kt = 0; kt < NKT; kt++) {
        const int cur = kt & 1;
        if (kt + 1 < NKT) {
            int k0 = (kt + 1) * 32;
            aR0 = *(const uint4*)(Ag + (size_t)ar0*DIM + k0 + ac);
            aR1 = *(const uint4*)(Ag + (size_t)ar1*DIM + k0 + ac);
            bR  = *(const uint4*)(Bg + (size_t)br *DIM + k0 + ac);
        }
        const uint32_t aB = aSm0 + cur * aBufStride;
        const uint32_t bB = bSm0 + cur * bBufStride;

        #pragma unroll
        for (int kh = 0; kh < 2; kh++) {
            uint32_t af[2][4];
            #pragma unroll
            for (int tm = 0; tm < 2; tm++) {
                uint32_t addr = aB + aoff + (uint32_t)(tm*16*RLD + kh*16) * 2;
                asm volatile(
                    "ldmatrix.sync.aligned.m8n8.x4.shared.b16 {%0,%1,%2,%3}, [%4];"
                    : "=r"(af[tm][0]), "=r"(af[tm][1]),
                      "=r"(af[tm][2]), "=r"(af[tm][3]) : "r"(addr));
            }
            uint32_t bf[4][2];
            #pragma unroll
            for (int tn = 0; tn < 4; tn++) {
                uint32_t addr = bB + boff + (uint32_t)(tn*8*RLD + kh*16) * 2;
                asm volatile(
                    "ldmatrix.sync.aligned.m8n8.x2.shared.b16 {%0,%1}, [%2];"
                    : "=r"(bf[tn][0]), "=r"(bf[tn][1]) : "r"(addr));
            }
            #pragma unroll
            for (int tm = 0; tm < 2; tm++)
                #pragma unroll
                for (int tn = 0; tn < 4; tn++) {
                    asm volatile(
                        "mma.sync.aligned.m16n8k16.row.col.f32.f16.f16.f32 "
                        "{%0,%1,%2,%3}, {%4,%5,%6,%7}, {%8,%9}, {%0,%1,%2,%3};"
                        : "+f"(acc[tm][tn][0]), "+f"(acc[tm][tn][1]),
                          "+f"(acc[tm][tn][2]), "+f"(acc[tm][tn][3])
                        : "r"(af[tm][0]), "r"(af[tm][1]),
                          "r"(af[tm][2]), "r"(af[tm][3]),
                          "r"(bf[tn][0]), "r"(bf[tn][1]));
                }
        }
        if (kt + 1 < NKT) {
            const int nxt = cur ^ 1;
            __syncthreads();
            *(uint4*)&As[nxt][ar0*RLD + ac] = aR0;
            *(uint4*)&As[nxt][ar1*RLD + ac] = aR1;
            *(uint4*)&Bs[nxt][br *RLD + ac] = bR;
            __syncthreads();
        }
    }

    const int gid = lane >> 2, tig = lane & 3;
    #pragma unroll
    for (int tm = 0; tm < 2; tm++) {
        int r0 = m0 + wm + tm*16 + gid;
        float bm0 = biasM[r0], bm8 = biasM[r0 + 8];
        #pragma unroll
        for (int tn = 0; tn < 4; tn++) {
            int col = n0 + wn + tn*8 + tig*2;
            float2 lo = make_float2(acc[tm][tn][0] + bm0, acc[tm][tn][1] + bm0);
            float2 hi = make_float2(acc[tm][tn][2] + bm8, acc[tm][tn][3] + bm8);
            *(float2*)&C[(size_t)r0*NSAMP + col]       = lo;
            *(float2*)&C[(size_t)(r0+8)*NSAMP + col]   = hi;
        }
    }
}

// ---------------------------------------------------------------------------
// Persistent sequential-scan kernel. 147 CTAs x 128 threads.
// Exchange: ONE 16B slot per CTA {7 x fp16 h, 16-bit tag}, gpu-scope, parity
// double-buffered. Threads 0..127 poll slot tid; threads 0..18 also slot tid+128.
// ---------------------------------------------------------------------------
#define SCAN_CTAS 147
#define SCAN_TPB  128
#define WS_HALFS  (LAYERS*28*1024)            // 114688 halves
#define WS_BYTES  (WS_HALFS*2)                // 229376 B
#define SCAN_SMEM (WS_BYTES + 2048 + (28+56)*4)   // + h_sm(fp16) + gdot + ga[2]

__device__ __forceinline__ float tanh_fast(float x) {
    float cx = fminf(fmaxf(x, -15.f), 15.f);
    float e  = __expf(2.f * cx);
    return __fdividef(e - 1.f, e + 1.f);
}
__device__ __forceinline__ float sigmoid_fast(float x) {
    return __fdividef(1.f, 1.f + __expf(-x));
}

// permuted h_sm position for h index j (matches the dot's uint4 access pattern)
__device__ __forceinline__ int hperm(int j) {
    return ((j >> 3) & 3)*256 + (j >> 5)*8 + (j & 7);
}

__global__ __launch_bounds__(SCAN_TPB, 1)
void scan_kernel(const float* __restrict__ Whh, const float* __restrict__ R,
                 float* __restrict__ Hbuf)
{
    extern __shared__ unsigned char smem[];
    __half* ws   = (__half*)smem;                         // [(l*28+rl)*1024 + perm]
    __half* h_sm = (__half*)(smem + WS_BYTES);            // [1024] permuted
    float*  gdot = (float*)(smem + WS_BYTES + 2048);      // [28]
    float*  ga   = gdot + 28;                             // [2][28]

    const int cta = blockIdx.x, tid = threadIdx.x;
    const int j0  = cta * 7;
    const int nj  = (j0 + 7 <= DIM) ? 7 : (DIM - j0);     // last CTA: 2

    // ---- fill SMEM weights (fp16, permuted: lane reads wr[m8*256+lane*8+b] = k(lane*32+m8*8+b))
    for (int p = tid; p < WS_HALFS; p += SCAN_TPB) {
        int rowblk = p >> 10;                   // l*28 + rl
        int l  = rowblk / 28, rl = rowblk - l*28;
        int off = p & 1023;
        int m8 = off >> 8, ln = (off >> 3) & 31, b = off & 7;
        int q = rl / 7, u = rl - q*7;
        float v = 0.f;
        if (u < nj) {
            int k = ln*32 + m8*8 + b;
            v = Whh[((size_t)l*4*DIM + q*DIM + j0 + u)*DIM + k];
        }
        ws[p] = __float2half(v);
    }
    __syncthreads();

    const int w = tid >> 5, lane = tid & 31;
    float cst = 0.f;                             // c state (warp0 lane u)

    // ---- poll-slot assignment: slot0 = tid (always); slot1 = tid+128 (tid<19)
    const bool has2 = (tid + 128 < NCTA);

    // ---- R prefetch bookkeeping (one step ahead)
    int pf_q = 0, pf_u = 0;
    bool pf_act = (tid < 28);
    if (pf_act) { pf_q = tid / 7; pf_u = tid - pf_q*7; pf_act = (pf_u < nj); }
    float a_cur = 0.f;
    if (pf_act)   // step g=1: i=0, l=0
        a_cur = R[((size_t)(pf_q*DIM + j0 + pf_u))*NSAMP + 0];

    #pragma unroll 1
    for (int g = 1; g <= NSTEP; ++g) {
        const int s = g - 1;
        const int i = s >> 2, l = s & 3;

        float a_nxt = 0.f;
        if (pf_act && g < NSTEP) {
            int i2 = g >> 2, l2 = g & 3;
            a_nxt = R[((size_t)(l2*4*DIM + pf_q*DIM + j0 + pf_u))*NSAMP + i2];
        }
        if (tid < 28) ga[(g & 1)*28 + tid] = a_cur;

        // ---- weight prefetch (m8=0 chunk of this step's 7 rows) during the wait
        uint4 wpre[7];
        #pragma unroll
        for (int t = 0; t < 7; t++) {
            const int rl = w + 4*t;
            wpre[t] = *(const uint4*)&ws[(((size_t)l*28 + rl) << 10) + lane*8];
        }

        // ---- single-slot poll: one dependent load chain per slot
        {
            const uint4* hb = g_hx + ((s & 1) * NCTA);
            const unsigned want = (unsigned)s;     // accept tag >= s
            uint4 v0, v1;
            bool f0 = false, f1 = !has2;
            do {
                if (!f0) { v0 = ldv4(hb + tid);        f0 = ((v0.w >> 16) >= want); }
                if (!f1) { v1 = ldv4(hb + tid + 128);  f1 = ((v1.w >> 16) >= want); }
            } while (!(f0 && f1));
            // unpack 7 fp16 h into permuted h_sm
            {
                int cb = tid * 7;
                unsigned short hs[7] = {
                    (unsigned short)(v0.x & 0xffff), (unsigned short)(v0.x >> 16),
                    (unsigned short)(v0.y & 0xffff), (unsigned short)(v0.y >> 16),
                    (unsigned short)(v0.z & 0xffff), (unsigned short)(v0.z >> 16),
                    (unsigned short)(v0.w & 0xffff) };
                #pragma unroll
                for (int d = 0; d < 7; d++) {
                    int j = cb + d;
                    if (j < DIM) h_sm[hperm(j)] = __ushort_as_half(hs[d]);
                }
            }
            if (has2) {
                int cb = (tid + 128) * 7;
                unsigned short hs[7] = {
                    (unsigned short)(v1.x & 0xffff), (unsigned short)(v1.x >> 16),
                    (unsigned short)(v1.y & 0xffff), (unsigned short)(v1.y >> 16),
                    (unsigned short)(v1.z & 0xffff), (unsigned short)(v1.z >> 16),
                    (unsigned short)(v1.w & 0xffff) };
                #pragma unroll
                for (int d = 0; d < 7; d++) {
                    int j = cb + d;
                    if (j < DIM) h_sm[hperm(j)] = __ushort_as_half(hs[d]);
                }
            }
        }
        __syncthreads();   // B1

        // ---- load h into registers: lane owns h[lane*32 .. +32)
        float hreg[32];
        #pragma unroll
        for (int m8 = 0; m8 < 4; m8++) {
            uint4 hv = *(const uint4*)&h_sm[m8*256 + lane*8];
            const __half2* h2 = (const __half2*)&hv;
            #pragma unroll
            for (int p2 = 0; p2 < 4; p2++) {
                float2 f = __half22float2(h2[p2]);
                hreg[m8*8 + p2*2]     = f.x;
                hreg[m8*8 + p2*2 + 1] = f.y;
            }
        }

        // ---- 7 rows per warp: rl = w + 4t (m8=0 from prefetched regs)
        float dotv[7];
        #pragma unroll
        for (int t = 0; t < 7; t++) {
            const int rl = w + 4*t;
            const __half* wr = ws + (((size_t)l*28 + rl) << 10);
            float acc = 0.f;
            {
                const __half2* w2 = (const __half2*)&wpre[t];
                #pragma unroll
                for (int p2 = 0; p2 < 4; p2++) {
                    float2 wf = __half22float2(w2[p2]);
                    acc += wf.x * hreg[p2*2] + wf.y * hreg[p2*2 + 1];
                }
            }
            #pragma unroll
            for (int m8 = 1; m8 < 4; m8++) {
                uint4 wv = *(const uint4*)&wr[m8*256 + lane*8];
                const __half2* w2 = (const __half2*)&wv;
                #pragma unroll
                for (int p2 = 0; p2 < 4; p2++) {
                    float2 wf = __half22float2(w2[p2]);
                    acc += wf.x * hreg[m8*8 + p2*2] + wf.y * hreg[m8*8 + p2*2 + 1];
                }
            }
            dotv[t] = acc;
        }
        #pragma unroll
        for (int t = 0; t < 7; t++) {
            float v = dotv[t];
            v += __shfl_xor_sync(0xffffffffu, v, 16);
            v += __shfl_xor_sync(0xffffffffu, v, 8);
            v += __shfl_xor_sync(0xffffffffu, v, 4);
            v += __shfl_xor_sync(0xffffffffu, v, 2);
            v += __shfl_xor_sync(0xffffffffu, v, 1);
            if (lane == 0) gdot[w + 4*t] = v;
        }
        __syncthreads();   // B2

        // ---- gate math + single-slot publish (warp 0)
        if (w == 0) {
            float h = 0.f;
            if (lane < nj) {
                const float* gav = ga + (g & 1)*28;
                float gi = gdot[lane]      + gav[lane];
                float gf = gdot[7 + lane]  + gav[7 + lane];
                float gg = gdot[14 + lane] + gav[14 + lane];
                float go = gdot[21 + lane] + gav[21 + lane];
                float I = sigmoid_fast(gi);
                float F = sigmoid_fast(gf);
                float G = tanh_fast(gg);
                cst = F * cst + I * G;
                float O = sigmoid_fast(go);
                h = O * tanh_fast(cst);
            }
            unsigned hu = (unsigned)__half_as_ushort(__float2half(h));
            unsigned q1 = __shfl_sync(0xffffffffu, hu, 1);
            unsigned q2 = __shfl_sync(0xffffffffu, hu, 2);
            unsigned q3 = __shfl_sync(0xffffffffu, hu, 3);
            unsigned q4 = __shfl_sync(0xffffffffu, hu, 4);
            unsigned q5 = __shfl_sync(0xffffffffu, hu, 5);
            unsigned q6 = __shfl_sync(0xffffffffu, hu, 6);
            if (lane == 0) {
                uint4 pk;
                pk.x = (hu & 0xffffu) | (q1 << 16);
                pk.y = (q2 & 0xffffu) | (q3 << 16);
                pk.z = (q4 & 0xffffu) | (q5 << 16);
                pk.w = (q6 & 0xffffu) | ((unsigned)g << 16);
                stv4(&g_hx[(g & 1)*NCTA + cta], pk);
            }
            if (lane < nj && l == 3)
                Hbuf[(size_t)i*DIM + j0 + lane] = h;
        }
        a_cur = a_nxt;
        // no trailing barrier: next step's poll self-synchronizes on tags
    }
}

// ---------------------------------------------------------------------------
// Launch
// ---------------------------------------------------------------------------
extern "C" void kernel_launch(void* const* d_in, const int* in_sizes, int n_in,
                              void* d_out, int out_size)
{
    const float* x      = (const float*)d_in[0];
    const int*   ts     = (const int*)  d_in[1];
    const float* proj_w = (const float*)d_in[2];
    const float* proj_b = (const float*)d_in[3];
    const float* te_w1  = (const float*)d_in[4];
    const float* te_b1  = (const float*)d_in[5];
    const float* te_w2  = (const float*)d_in[6];
    const float* te_b2  = (const float*)d_in[7];
    const float* Wih    = (const float*)d_in[8];
    const float* Whh    = (const float*)d_in[9];
    const float* bih    = (const float*)d_in[10];
    const float* bhh    = (const float*)d_in[11];
    const float* lin_w  = (const float*)d_in[12];
    const float* lin_b  = (const float*)d_in[13];
    float* out = (float*)d_out;

    float *PE, *T1, *EMB, *XP, *R, *H, *BS;
    __half *WihH, *XPH;
    cudaGetSymbolAddress((void**)&PE,  g_PE);
    cudaGetSymbolAddress((void**)&T1,  g_T1);
    cudaGetSymbolAddress((void**)&EMB, g_EMB);
    cudaGetSymbolAddress((void**)&XP,  g_XP);
    cudaGetSymbolAddress((void**)&R,   g_R);
    cudaGetSymbolAddress((void**)&H,   g_H);
    cudaGetSymbolAddress((void**)&BS,  g_BS);
    cudaGetSymbolAddress((void**)&WihH, g_WihH);
    cudaGetSymbolAddress((void**)&XPH,  g_XPH);

    cudaFuncSetAttribute(scan_kernel, cudaFuncAttributeMaxDynamicSharedMemorySize,
                         SCAN_SMEM);

    // 1) sinusoidal PE
    pe_kernel<<<NSAMP, 128>>>(ts, PE);
    // 2) T1 = silu(PE @ te_w1^T + te_b1)
    gemm_nt<<<dim3(DIM/128, NSAMP/128), 256>>>(PE, te_w1, T1, NSAMP, DIM, DIM,
                                               nullptr, te_b1, nullptr, 1);
    // 3) EMB = T1 @ te_w2^T + te_b2
    gemm_nt<<<dim3(DIM/128, NSAMP/128), 256>>>(T1, te_w2, EMB, NSAMP, DIM, DIM,
                                               nullptr, te_b2, nullptr, 0);
    // 4) XP = x @ proj_w^T + proj_b + EMB
    gemm_nt<<<dim3(DIM/128, NSAMP/128), 256>>>(x, proj_w, XP, NSAMP, DIM, DIM,
                                               nullptr, proj_b, EMB, 0);
    // 5) stacked gate bias
    bias_kernel<<<GROWS/256, 256>>>(bih, bhh, BS);
    // 6) fp16 conversions for the tensor-core R GEMM
    conv_fp16_kernel<<<((GROWS*DIM/4)+255)/256, 256>>>(Wih, WihH, GROWS*DIM/4);
    conv_fp16_kernel<<<((NSAMP*DIM/4)+255)/256, 256>>>(XP, XPH, NSAMP*DIM/4);
    // 7) R = Wih_stack @ XP^T + bias   (16384 x 4096 x 1024) — fp16 HMMA
    gemm_r_fp16<<<dim3(NSAMP/64, GROWS/128), 256>>>(WihH, XPH, BS, R);
    // 8) reset tagged h slots (graph-replay safe)
    reset_kernel<<<(2*NCTA+255)/256, 256>>>();
    // 9) persistent sequential scan
    scan_kernel<<<SCAN_CTAS, SCAN_TPB, SCAN_SMEM>>>(Whh, R, H);
    // 10) out = H @ lin_w^T + lin_b (fp32 — output precision)
    gemm_nt<<<dim3(DIM/128, NSAMP/128), 256>>>(H, lin_w, out, NSAMP, DIM, DIM,
                                               nullptr, lin_b, nullptr, 0);
}

// round 14
// speedup vs baseline: 1.2223x; 1.2223x over previous
#include <cuda_runtime.h>
#include <cuda_fp16.h>
#include <cstdint>

// ---------------------------------------------------------------------------
// Problem constants
// ---------------------------------------------------------------------------
#define NSAMP 4096
#define DIM   1024     // IN == HID == DIM_T
#define LAYERS 4
#define GROWS (LAYERS*4*DIM)       // 16384 stacked gate rows
#define NSTEP (NSAMP*LAYERS)       // 16384 sequential steps
#define NSLOT 441                  // 147 CTAs * 3 slots (3 h values + tag each)

// ---------------------------------------------------------------------------
// Scratch (static device globals; no runtime allocation)
// ---------------------------------------------------------------------------
__device__ float g_PE [(size_t)NSAMP*DIM];
__device__ float g_T1 [(size_t)NSAMP*DIM];
__device__ float g_EMB[(size_t)NSAMP*DIM];
__device__ float g_XP [(size_t)NSAMP*DIM];
__device__ float g_R  [(size_t)GROWS*NSAMP];   // 256 MB: R[row, i]
__device__ float g_H  [(size_t)NSAMP*DIM];
__device__ float g_BS [GROWS];
__device__ __half g_WihH[(size_t)GROWS*DIM];   // 32 MB fp16 Wih
__device__ __half g_XPH [(size_t)NSAMP*DIM];   // 8 MB fp16 XP
// Tagged-quad h exchange, double-buffered by step parity.
// Slot = {h0,h1,h2, tag}. Buffer b holds steps with (g&1)==b.
__device__ uint4 g_hx[2*NSLOT];

// ---------------------------------------------------------------------------
// 16B GPU-scope vector ld/st (performed at L2; no SYS/C2C coherence cost)
// ---------------------------------------------------------------------------
__device__ __forceinline__ uint4 ldv4(const uint4* p) {
    uint4 v;
    asm volatile("ld.relaxed.gpu.global.v4.u32 {%0,%1,%2,%3}, [%4];"
                 : "=r"(v.x), "=r"(v.y), "=r"(v.z), "=r"(v.w) : "l"(p) : "memory");
    return v;
}
__device__ __forceinline__ void stv4(uint4* p, uint4 v) {
    asm volatile("st.relaxed.gpu.global.v4.u32 [%0], {%1,%2,%3,%4};"
                 :: "l"(p), "r"(v.x), "r"(v.y), "r"(v.z), "r"(v.w) : "memory");
}

// ---------------------------------------------------------------------------
// Small prologue kernels
// ---------------------------------------------------------------------------
__global__ void pe_kernel(const int* __restrict__ ts, float* __restrict__ PE) {
    int i = blockIdx.x;
    float t = (float)ts[i];
    for (int d = threadIdx.x; d < DIM/2; d += blockDim.x) {
        float f = expf((float)d * (-9.210340371976184f / (float)(DIM/2 - 1)));
        float a = t * f;
        PE[(size_t)i*DIM + d]          = sinf(a);
        PE[(size_t)i*DIM + DIM/2 + d]  = cosf(a);
    }
}

__global__ void bias_kernel(const float* __restrict__ bih, const float* __restrict__ bhh,
                            float* __restrict__ out) {
    int idx = blockIdx.x*blockDim.x + threadIdx.x;
    if (idx < GROWS) out[idx] = bih[idx] + bhh[idx];
}

__global__ void reset_kernel() {
    int idx = blockIdx.x*blockDim.x + threadIdx.x;
    if (idx < 2*NSLOT) g_hx[idx] = make_uint4(0u, 0u, 0u, 0u);  // tag 0, h = 0
}

__global__ void conv_fp16_kernel(const float* __restrict__ src,
                                 __half* __restrict__ dst, int n4) {
    int i = blockIdx.x*blockDim.x + threadIdx.x;
    if (i < n4) {
        float4 v = *(const float4*)&src[(size_t)i*4];
        __half o[4];
        o[0] = __float2half_rn(v.x);
        o[1] = __float2half_rn(v.y);
        o[2] = __float2half_rn(v.z);
        o[3] = __float2half_rn(v.w);
        *(uint2*)&dst[(size_t)i*4] = *(uint2*)o;
    }
}

// ---------------------------------------------------------------------------
// Generic NT GEMM (fp32 SIMT) for the small GEMMs: C = A@B^T (+bias/add/silu)
// ---------------------------------------------------------------------------
__global__ __launch_bounds__(256, 2)
void gemm_nt(const float* __restrict__ A, const float* __restrict__ B,
             float* __restrict__ C, int M, int N, int K,
             const float* __restrict__ biasM, const float* __restrict__ biasN,
             const float* __restrict__ addMN, int do_silu)
{
    const int BM = 128, BK = 16;
    __shared__ float As[2][16][128+8];
    __shared__ float Bs[2][16][128+8];

    const int tid = threadIdx.x;
    const int m0 = blockIdx.y * BM, n0 = blockIdx.x * BM;
    const int tx = tid & 15, ty = tid >> 4;

    float4 aF[2], bF[2];

    #pragma unroll
    for (int i = 0; i < 2; i++) {
        int f = tid + i*256;
        int row = f >> 2, c4 = (f & 3) * 4;
        aF[i] = *(const float4*)&A[(size_t)(m0+row)*K + c4];
        bF[i] = *(const float4*)&B[(size_t)(n0+row)*K + c4];
    }
    #pragma unroll
    for (int i = 0; i < 2; i++) {
        int f = tid + i*256;
        int row = f >> 2, c4 = (f & 3) * 4;
        As[0][c4+0][row] = aF[i].x; As[0][c4+1][row] = aF[i].y;
        As[0][c4+2][row] = aF[i].z; As[0][c4+3][row] = aF[i].w;
        Bs[0][c4+0][row] = bF[i].x; Bs[0][c4+1][row] = bF[i].y;
        Bs[0][c4+2][row] = bF[i].z; Bs[0][c4+3][row] = bF[i].w;
    }
    __syncthreads();

    float acc[8][8];
    #pragma unroll
    for (int i = 0; i < 8; i++)
        #pragma unroll
        for (int j = 0; j < 8; j++) acc[i][j] = 0.f;

    const int nk = K / BK;
    for (int kt = 0; kt < nk; kt++) {
        const int cur = kt & 1;
        if (kt + 1 < nk) {
            int k0 = (kt+1)*BK;
            #pragma unroll
            for (int i = 0; i < 2; i++) {
                int f = tid + i*256;
                int row = f >> 2, c4 = (f & 3) * 4;
                aF[i] = *(const float4*)&A[(size_t)(m0+row)*K + k0 + c4];
                bF[i] = *(const float4*)&B[(size_t)(n0+row)*K + k0 + c4];
            }
        }
        #pragma unroll
        for (int k = 0; k < BK; k++) {
            float a[8], b[8];
            *(float4*)&a[0] = *(const float4*)&As[cur][k][ty*8];
            *(float4*)&a[4] = *(const float4*)&As[cur][k][ty*8+4];
            *(float4*)&b[0] = *(const float4*)&Bs[cur][k][tx*8];
            *(float4*)&b[4] = *(const float4*)&Bs[cur][k][tx*8+4];
            #pragma unroll
            for (int i = 0; i < 8; i++)
                #pragma unroll
                for (int j = 0; j < 8; j++)
                    acc[i][j] += a[i] * b[j];
        }
        if (kt + 1 < nk) {
            const int nxt = cur ^ 1;
            #pragma unroll
            for (int i = 0; i < 2; i++) {
                int f = tid + i*256;
                int row = f >> 2, c4 = (f & 3) * 4;
                As[nxt][c4+0][row] = aF[i].x; As[nxt][c4+1][row] = aF[i].y;
                As[nxt][c4+2][row] = aF[i].z; As[nxt][c4+3][row] = aF[i].w;
                Bs[nxt][c4+0][row] = bF[i].x; Bs[nxt][c4+1][row] = bF[i].y;
                Bs[nxt][c4+2][row] = bF[i].z; Bs[nxt][c4+3][row] = bF[i].w;
            }
            __syncthreads();
        }
    }

    #pragma unroll
    for (int i = 0; i < 8; i++) {
        int m = m0 + ty*8 + i;
        float bm = biasM ? biasM[m] : 0.f;
        #pragma unroll
        for (int j = 0; j < 8; j++) {
            int n = n0 + tx*8 + j;
            float v = acc[i][j] + bm;
            if (biasN) v += biasN[n];
            if (addMN) v += addMN[(size_t)m*N + n];
            if (do_silu) v = v / (1.f + __expf(-v));
            C[(size_t)m*N + n] = v;
        }
    }
}

// ---------------------------------------------------------------------------
// fp16 tensor-core GEMM for R:  C[16384,4096] = A[16384,1024] @ B[4096,1024]^T + biasM
// NT GEMM, both operands k-major -> BOTH sides use NON-TRANS ldmatrix.
// ---------------------------------------------------------------------------
#define RLD 40    // padded halves per SMEM row

__global__ __launch_bounds__(256, 2)
void gemm_r_fp16(const __half* __restrict__ A,
                 const __half* __restrict__ B,
                 const float* __restrict__ biasM,
                 float* __restrict__ C)
{
    __shared__ __align__(16) unsigned short As[2][128*RLD];
    __shared__ __align__(16) unsigned short Bs[2][64*RLD];

    const int tid = threadIdx.x;
    const int m0 = blockIdx.y * 128;
    const int n0 = blockIdx.x * 64;
    const int w  = tid >> 5, lane = tid & 31;
    const int wm = (w & 3) * 32;
    const int wn = (w >> 2) * 32;

    const int ar0 = tid >> 2,          ac = (tid & 3) * 8;
    const int ar1 = (tid >> 2) + 64;
    const int br  = tid >> 2;

    const __half* Ag = A + (size_t)m0*DIM;
    const __half* Bg = B + (size_t)n0*DIM;

    uint4 aR0 = *(const uint4*)(Ag + (size_t)ar0*DIM + ac);
    uint4 aR1 = *(const uint4*)(Ag + (size_t)ar1*DIM + ac);
    uint4 bR  = *(const uint4*)(Bg + (size_t)br *DIM + ac);
    *(uint4*)&As[0][ar0*RLD + ac] = aR0;
    *(uint4*)&As[0][ar1*RLD + ac] = aR1;
    *(uint4*)&Bs[0][br *RLD + ac] = bR;
    __syncthreads();

    float acc[2][4][4];
    #pragma unroll
    for (int tm = 0; tm < 2; tm++)
        #pragma unroll
        for (int tn = 0; tn < 4; tn++)
            #pragma unroll
            for (int e = 0; e < 4; e++) acc[tm][tn][e] = 0.f;

    const uint32_t aoff = ((uint32_t)(wm + (lane & 15)) * RLD + (lane >> 4) * 8) * 2;
    const uint32_t boff = ((uint32_t)(wn + (lane & 7))  * RLD + ((lane >> 3) & 1) * 8) * 2;
    const uint32_t aSm0 = (uint32_t)__cvta_generic_to_shared(&As[0][0]);
    const uint32_t bSm0 = (uint32_t)__cvta_generic_to_shared(&Bs[0][0]);
    const uint32_t aBufStride = 128*RLD*2;
    const uint32_t bBufStride = 64*RLD*2;

    const int NKT = DIM / 32;
    for (int kt = 0; kt < NKT; kt++) {
        const int cur = kt & 1;
        if (kt + 1 < NKT) {
            int k0 = (kt + 1) * 32;
            aR0 = *(const uint4*)(Ag + (size_t)ar0*DIM + k0 + ac);
            aR1 = *(const uint4*)(Ag + (size_t)ar1*DIM + k0 + ac);
            bR  = *(const uint4*)(Bg + (size_t)br *DIM + k0 + ac);
        }
        const uint32_t aB = aSm0 + cur * aBufStride;
        const uint32_t bB = bSm0 + cur * bBufStride;

        #pragma unroll
        for (int kh = 0; kh < 2; kh++) {
            uint32_t af[2][4];
            #pragma unroll
            for (int tm = 0; tm < 2; tm++) {
                uint32_t addr = aB + aoff + (uint32_t)(tm*16*RLD + kh*16) * 2;
                asm volatile(
                    "ldmatrix.sync.aligned.m8n8.x4.shared.b16 {%0,%1,%2,%3}, [%4];"
                    : "=r"(af[tm][0]), "=r"(af[tm][1]),
                      "=r"(af[tm][2]), "=r"(af[tm][3]) : "r"(addr));
            }
            uint32_t bf[4][2];
            #pragma unroll
            for (int tn = 0; tn < 4; tn++) {
                uint32_t addr = bB + boff + (uint32_t)(tn*8*RLD + kh*16) * 2;
                asm volatile(
                    "ldmatrix.sync.aligned.m8n8.x2.shared.b16 {%0,%1}, [%2];"
                    : "=r"(bf[tn][0]), "=r"(bf[tn][1]) : "r"(addr));
            }
            #pragma unroll
            for (int tm = 0; tm < 2; tm++)
                #pragma unroll
                for (int tn = 0; tn < 4; tn++) {
                    asm volatile(
                        "mma.sync.aligned.m16n8k16.row.col.f32.f16.f16.f32 "
                        "{%0,%1,%2,%3}, {%4,%5,%6,%7}, {%8,%9}, {%0,%1,%2,%3};"
                        : "+f"(acc[tm][tn][0]), "+f"(acc[tm][tn][1]),
                          "+f"(acc[tm][tn][2]), "+f"(acc[tm][tn][3])
                        : "r"(af[tm][0]), "r"(af[tm][1]),
                          "r"(af[tm][2]), "r"(af[tm][3]),
                          "r"(bf[tn][0]), "r"(bf[tn][1]));
                }
        }
        if (kt + 1 < NKT) {
            const int nxt = cur ^ 1;
            __syncthreads();
            *(uint4*)&As[nxt][ar0*RLD + ac] = aR0;
            *(uint4*)&As[nxt][ar1*RLD + ac] = aR1;
            *(uint4*)&Bs[nxt][br *RLD + ac] = bR;
            __syncthreads();
        }
    }

    const int gid = lane >> 2, tig = lane & 3;
    #pragma unroll
    for (int tm = 0; tm < 2; tm++) {
        int r0 = m0 + wm + tm*16 + gid;
        float bm0 = biasM[r0], bm8 = biasM[r0 + 8];
        #pragma unroll
        for (int tn = 0; tn < 4; tn++) {
            int col = n0 + wn + tn*8 + tig*2;
            float2 lo = make_float2(acc[tm][tn][0] + bm0, acc[tm][tn][1] + bm0);
            float2 hi = make_float2(acc[tm][tn][2] + bm8, acc[tm][tn][3] + bm8);
            *(float2*)&C[(size_t)r0*NSAMP + col]       = lo;
            *(float2*)&C[(size_t)(r0+8)*NSAMP + col]   = hi;
        }
    }
}

// ---------------------------------------------------------------------------
// Persistent sequential-scan kernel (R12 config: 147 CTAs x 128 threads,
// tagged-quad 441-slot exchange, gpu-scope ld/st, sticky-fresh poll).
// ONLY change vs R12: the dot inner product uses HFMA2 chains (len 4) with a
// per-row fp32 flush — ~half the instruction stream of the cvt+FFMA version.
// ---------------------------------------------------------------------------
#define SCAN_CTAS 147
#define SCAN_TPB  128
#define WS_HALFS  (LAYERS*28*1024)            // 114688 halves
#define WS_BYTES  (WS_HALFS*2)                // 229376 B
#define SCAN_SMEM (WS_BYTES + 2048 + (28+56)*4)   // + h_sm(fp16) + gdot + ga[2]

__device__ __forceinline__ float tanh_fast(float x) {
    float cx = fminf(fmaxf(x, -15.f), 15.f);
    float e  = __expf(2.f * cx);
    return __fdividef(e - 1.f, e + 1.f);
}
__device__ __forceinline__ float sigmoid_fast(float x) {
    return __fdividef(1.f, 1.f + __expf(-x));
}

__global__ __launch_bounds__(SCAN_TPB, 1)
void scan_kernel(const float* __restrict__ Whh, const float* __restrict__ R,
                 float* __restrict__ Hbuf)
{
    extern __shared__ unsigned char smem[];
    __half* ws   = (__half*)smem;                         // [(l*28+rl)*1024 + perm]
    __half* h_sm = (__half*)(smem + WS_BYTES);            // [1024] permuted
    float*  gdot = (float*)(smem + WS_BYTES + 2048);      // [28]
    float*  ga   = gdot + 28;                             // [2][28]

    const int cta = blockIdx.x, tid = threadIdx.x;
    const int j0  = cta * 7;
    const int nj  = (j0 + 7 <= DIM) ? 7 : (DIM - j0);     // last CTA: 2

    for (int p = tid; p < WS_HALFS; p += SCAN_TPB) {
        int rowblk = p >> 10;                   // l*28 + rl
        int l  = rowblk / 28, rl = rowblk - l*28;
        int off = p & 1023;
        int m8 = off >> 8, ln = (off >> 3) & 31, b = off & 7;
        int q = rl / 7, u = rl - q*7;
        float v = 0.f;
        if (u < nj) {
            int k = ln*32 + m8*8 + b;
            v = Whh[((size_t)l*4*DIM + q*DIM + j0 + u)*DIM + k];
        }
        ws[p] = __float2half(v);
    }
    __syncthreads();

    const int w = tid >> 5, lane = tid & 31;
    float cst = 0.f;                             // c state (warp0 lane u)

    // ---- per-thread poll-slot assignment (static)
    int nsl = 0;
    int      sid4[4];
    int      jb4 [4];
    int      dm4 [4];
    #pragma unroll
    for (int k = 0; k < 4; k++) {
        int s = tid + 128*k;
        if (s < NSLOT) {
            int cs = s / 3, r = s - 3*cs;
            int jb = cs*7 + r*3;
            if (jb < DIM) {
                int njc = (cs*7 + 7 <= DIM) ? 7 : (DIM - cs*7);
                int dm = njc - r*3; if (dm > 3) dm = 3;
                if (dm > 0) { sid4[nsl] = s; jb4[nsl] = jb; dm4[nsl] = dm; nsl++; }
            }
        }
    }

    // ---- R prefetch bookkeeping (one step ahead)
    int pf_q = 0, pf_u = 0;
    bool pf_act = (tid < 28);
    if (pf_act) { pf_q = tid / 7; pf_u = tid - pf_q*7; pf_act = (pf_u < nj); }
    float a_cur = 0.f;
    if (pf_act)   // step g=1: i=0, l=0
        a_cur = R[((size_t)(pf_q*DIM + j0 + pf_u))*NSAMP + 0];

    #pragma unroll 1
    for (int g = 1; g <= NSTEP; ++g) {
        const int s = g - 1;
        const int i = s >> 2, l = s & 3;

        float a_nxt = 0.f;
        if (pf_act && g < NSTEP) {
            int i2 = g >> 2, l2 = g & 3;
            a_nxt = R[((size_t)(l2*4*DIM + pf_q*DIM + j0 + pf_u))*NSAMP + i2];
        }
        if (tid < 28) ga[(g & 1)*28 + tid] = a_cur;

        // ---- tagged-quad poll (sticky per-slot freshness)
        {
            const uint4* hb = g_hx + ((s & 1) * NSLOT);
            const unsigned want = (unsigned)s;     // accept tag >= s
            uint4 vv[4];
            unsigned fresh = 0;
            const unsigned all = (1u << nsl) - 1u;
            do {
                #pragma unroll
                for (int k = 0; k < 4; k++) if (k < nsl) {
                    if (!(fresh & (1u << k))) {
                        vv[k] = ldv4(hb + sid4[k]);
                        if (vv[k].w >= want) fresh |= (1u << k);
                    }
                }
            } while (fresh != all);
            #pragma unroll
            for (int k = 0; k < 4; k++) if (k < nsl) {
                unsigned dat[3] = { vv[k].x, vv[k].y, vv[k].z };
                #pragma unroll
                for (int d = 0; d < 3; d++) if (d < dm4[k]) {
                    int j = jb4[k] + d;
                    int p = ((j >> 3) & 3)*256 + (j >> 5)*8 + (j & 7);
                    h_sm[p] = __float2half(__uint_as_float(dat[d]));
                }
            }
        }
        __syncthreads();   // B1

        // ---- load h as half2 (no conversion): lane owns h[lane*32 .. +32)
        __half2 hh[16];
        #pragma unroll
        for (int m8 = 0; m8 < 4; m8++)
            *(uint4*)&hh[m8*4] = *(const uint4*)&h_sm[m8*256 + lane*8];

        // ---- 7 rows per warp, HFMA2 chains (len 4) + per-row fp32 flush
        const __half2 hz = __float2half2_rn(0.f);
        float dotv[7];
        #pragma unroll
        for (int t = 0; t < 7; t++) {
            const int rl = w + 4*t;
            const __half* wr = ws + (((size_t)l*28 + rl) << 10);
            __half2 ac0 = hz, ac1 = hz, ac2 = hz, ac3 = hz;
            #pragma unroll
            for (int m8 = 0; m8 < 4; m8++) {
                uint4 wv = *(const uint4*)&wr[m8*256 + lane*8];
                const __half2* w2 = (const __half2*)&wv;
                ac0 = __hfma2(w2[0], hh[m8*4+0], ac0);
                ac1 = __hfma2(w2[1], hh[m8*4+1], ac1);
                ac2 = __hfma2(w2[2], hh[m8*4+2], ac2);
                ac3 = __hfma2(w2[3], hh[m8*4+3], ac3);
            }
            float2 f0 = __half22float2(ac0);
            float2 f1 = __half22float2(ac1);
            float2 f2 = __half22float2(ac2);
            float2 f3 = __half22float2(ac3);
            dotv[t] = (f0.x + f0.y) + (f1.x + f1.y)
                    + (f2.x + f2.y) + (f3.x + f3.y);
        }
        #pragma unroll
        for (int t = 0; t < 7; t++) {
            float v = dotv[t];
            v += __shfl_xor_sync(0xffffffffu, v, 16);
            v += __shfl_xor_sync(0xffffffffu, v, 8);
            v += __shfl_xor_sync(0xffffffffu, v, 4);
            v += __shfl_xor_sync(0xffffffffu, v, 2);
            v += __shfl_xor_sync(0xffffffffu, v, 1);
            if (lane == 0) gdot[w + 4*t] = v;
        }
        __syncthreads();   // B2

        if (w == 0) {
            float h = 0.f;
            if (lane < nj) {
                const float* gav = ga + (g & 1)*28;
                float gi = gdot[lane]      + gav[lane];
                float gf = gdot[7 + lane]  + gav[7 + lane];
                float gg = gdot[14 + lane] + gav[14 + lane];
                float go = gdot[21 + lane] + gav[21 + lane];
                float I = sigmoid_fast(gi);
                float F = sigmoid_fast(gf);
                float G = tanh_fast(gg);
                cst = F * cst + I * G;
                float O = sigmoid_fast(go);
                h = O * tanh_fast(cst);
            }
            float p0 = __shfl_sync(0xffffffffu, h, (3*lane)     & 31);
            float p1 = __shfl_sync(0xffffffffu, h, (3*lane + 1) & 31);
            float p2 = __shfl_sync(0xffffffffu, h, (3*lane + 2) & 31);
            if (lane < 3 && 3*lane < nj) {
                uint4 pk;
                pk.x = __float_as_uint(p0);
                pk.y = __float_as_uint(p1);
                pk.z = __float_as_uint(p2);
                pk.w = (unsigned)g;
                stv4(&g_hx[(g & 1)*NSLOT + cta*3 + lane], pk);
            }
            if (lane < nj && l == 3)
                Hbuf[(size_t)i*DIM + j0 + lane] = h;
        }
        a_cur = a_nxt;
    }
}

// ---------------------------------------------------------------------------
// Launch
// ---------------------------------------------------------------------------
extern "C" void kernel_launch(void* const* d_in, const int* in_sizes, int n_in,
                              void* d_out, int out_size)
{
    const float* x      = (const float*)d_in[0];
    const int*   ts     = (const int*)  d_in[1];
    const float* proj_w = (const float*)d_in[2];
    const float* proj_b = (const float*)d_in[3];
    const float* te_w1  = (const float*)d_in[4];
    const float* te_b1  = (const float*)d_in[5];
    const float* te_w2  = (const float*)d_in[6];
    const float* te_b2  = (const float*)d_in[7];
    const float* Wih    = (const float*)d_in[8];
    const float* Whh    = (const float*)d_in[9];
    const float* bih    = (const float*)d_in[10];
    const float* bhh    = (const float*)d_in[11];
    const float* lin_w  = (const float*)d_in[12];
    const float* lin_b  = (const float*)d_in[13];
    float* out = (float*)d_out;

    float *PE, *T1, *EMB, *XP, *R, *H, *BS;
    __half *WihH, *XPH;
    cudaGetSymbolAddress((void**)&PE,  g_PE);
    cudaGetSymbolAddress((void**)&T1,  g_T1);
    cudaGetSymbolAddress((void**)&EMB, g_EMB);
    cudaGetSymbolAddress((void**)&XP,  g_XP);
    cudaGetSymbolAddress((void**)&R,   g_R);
    cudaGetSymbolAddress((void**)&H,   g_H);
    cudaGetSymbolAddress((void**)&BS,  g_BS);
    cudaGetSymbolAddress((void**)&WihH, g_WihH);
    cudaGetSymbolAddress((void**)&XPH,  g_XPH);

    cudaFuncSetAttribute(scan_kernel, cudaFuncAttributeMaxDynamicSharedMemorySize,
                         SCAN_SMEM);

    // 1) sinusoidal PE
    pe_kernel<<<NSAMP, 128>>>(ts, PE);
    // 2) T1 = silu(PE @ te_w1^T + te_b1)
    gemm_nt<<<dim3(DIM/128, NSAMP/128), 256>>>(PE, te_w1, T1, NSAMP, DIM, DIM,
                                               nullptr, te_b1, nullptr, 1);
    // 3) EMB = T1 @ te_w2^T + te_b2
    gemm_nt<<<dim3(DIM/128, NSAMP/128), 256>>>(T1, te_w2, EMB, NSAMP, DIM, DIM,
                                               nullptr, te_b2, nullptr, 0);
    // 4) XP = x @ proj_w^T + proj_b + EMB
    gemm_nt<<<dim3(DIM/128, NSAMP/128), 256>>>(x, proj_w, XP, NSAMP, DIM, DIM,
                                               nullptr, proj_b, EMB, 0);
    // 5) stacked gate bias
    bias_kernel<<<GROWS/256, 256>>>(bih, bhh, BS);
    // 6) fp16 conversions for the tensor-core R GEMM
    conv_fp16_kernel<<<((GROWS*DIM/4)+255)/256, 256>>>(Wih, WihH, GROWS*DIM/4);
    conv_fp16_kernel<<<((NSAMP*DIM/4)+255)/256, 256>>>(XP, XPH, NSAMP*DIM/4);
    // 7) R = Wih_stack @ XP^T + bias   (16384 x 4096 x 1024) — fp16 HMMA
    gemm_r_fp16<<<dim3(NSAMP/64, GROWS/128), 256>>>(WihH, XPH, BS, R);
    // 8) reset tagged h slots (graph-replay safe)
    reset_kernel<<<(2*NSLOT+255)/256, 256>>>();
    // 9) persistent sequential scan
    scan_kernel<<<SCAN_CTAS, SCAN_TPB, SCAN_SMEM>>>(Whh, R, H);
    // 10) out = H @ lin_w^T + lin_b (fp32 — output precision)
    gemm_nt<<<dim3(DIM/128, NSAMP/128), 256>>>(H, lin_w, out, NSAMP, DIM, DIM,
                                               nullptr, lin_b, nullptr, 0);
}

// round 15
// speedup vs baseline: 1.3277x; 1.0862x over previous
#include <cuda_runtime.h>
#include <cuda_fp16.h>
#include <cstdint>

// ---------------------------------------------------------------------------
// Problem constants
// ---------------------------------------------------------------------------
#define NSAMP 4096
#define DIM   1024     // IN == HID == DIM_T
#define LAYERS 4
#define GROWS (LAYERS*4*DIM)       // 16384 stacked gate rows
#define NSTEP (NSAMP*LAYERS)       // 16384 sequential steps
#define NSLOT 441                  // 147 CTAs * 3 slots (3 h values + tag each)

// ---------------------------------------------------------------------------
// Scratch (static device globals; no runtime allocation)
// ---------------------------------------------------------------------------
__device__ float g_PE [(size_t)NSAMP*DIM];
__device__ float g_T1 [(size_t)NSAMP*DIM];
__device__ float g_EMB[(size_t)NSAMP*DIM];
__device__ float g_XP [(size_t)NSAMP*DIM];
__device__ float g_R  [(size_t)GROWS*NSAMP];   // 256 MB: R[row, i]
__device__ float g_H  [(size_t)NSAMP*DIM];
__device__ float g_BS [GROWS];
__device__ __half g_WihH[(size_t)GROWS*DIM];   // 32 MB fp16 Wih
__device__ __half g_XPH [(size_t)NSAMP*DIM];   // 8 MB fp16 XP
// Tagged-quad h exchange, double-buffered by step parity.
// Slot = {h0,h1,h2, tag}. Buffer b holds steps with (g&1)==b.
__device__ uint4 g_hx[2*NSLOT];

// ---------------------------------------------------------------------------
// 16B GPU-scope vector ld/st (performed at L2; no SYS/C2C coherence cost)
// ---------------------------------------------------------------------------
__device__ __forceinline__ uint4 ldv4(const uint4* p) {
    uint4 v;
    asm volatile("ld.relaxed.gpu.global.v4.u32 {%0,%1,%2,%3}, [%4];"
                 : "=r"(v.x), "=r"(v.y), "=r"(v.z), "=r"(v.w) : "l"(p) : "memory");
    return v;
}
__device__ __forceinline__ void stv4(uint4* p, uint4 v) {
    asm volatile("st.relaxed.gpu.global.v4.u32 [%0], {%1,%2,%3,%4};"
                 :: "l"(p), "r"(v.x), "r"(v.y), "r"(v.z), "r"(v.w) : "memory");
}

__device__ __forceinline__ float tanh_hw(float x) {
    float y;
    asm("tanh.approx.f32 %0, %1;" : "=f"(y) : "f"(x));
    return y;
}
__device__ __forceinline__ float sigmoid_hw(float x) {
    return 0.5f + 0.5f * tanh_hw(0.5f * x);
}

// ---------------------------------------------------------------------------
// Small prologue kernels
// ---------------------------------------------------------------------------
__global__ void pe_kernel(const int* __restrict__ ts, float* __restrict__ PE) {
    int i = blockIdx.x;
    float t = (float)ts[i];
    for (int d = threadIdx.x; d < DIM/2; d += blockDim.x) {
        float f = expf((float)d * (-9.210340371976184f / (float)(DIM/2 - 1)));
        float a = t * f;
        PE[(size_t)i*DIM + d]          = sinf(a);
        PE[(size_t)i*DIM + DIM/2 + d]  = cosf(a);
    }
}

__global__ void bias_kernel(const float* __restrict__ bih, const float* __restrict__ bhh,
                            float* __restrict__ out) {
    int idx = blockIdx.x*blockDim.x + threadIdx.x;
    if (idx < GROWS) out[idx] = bih[idx] + bhh[idx];
}

__global__ void reset_kernel() {
    int idx = blockIdx.x*blockDim.x + threadIdx.x;
    if (idx < 2*NSLOT) g_hx[idx] = make_uint4(0u, 0u, 0u, 0u);  // tag 0, h = 0
}

__global__ void conv_fp16_kernel(const float* __restrict__ src,
                                 __half* __restrict__ dst, int n4) {
    int i = blockIdx.x*blockDim.x + threadIdx.x;
    if (i < n4) {
        float4 v = *(const float4*)&src[(size_t)i*4];
        __half o[4];
        o[0] = __float2half_rn(v.x);
        o[1] = __float2half_rn(v.y);
        o[2] = __float2half_rn(v.z);
        o[3] = __float2half_rn(v.w);
        *(uint2*)&dst[(size_t)i*4] = *(uint2*)o;
    }
}

// ---------------------------------------------------------------------------
// Generic NT GEMM (fp32 SIMT) for the small GEMMs: C = A@B^T (+bias/add/silu)
// ---------------------------------------------------------------------------
__global__ __launch_bounds__(256, 2)
void gemm_nt(const float* __restrict__ A, const float* __restrict__ B,
             float* __restrict__ C, int M, int N, int K,
             const float* __restrict__ biasM, const float* __restrict__ biasN,
             const float* __restrict__ addMN, int do_silu)
{
    const int BM = 128, BK = 16;
    __shared__ float As[2][16][128+8];
    __shared__ float Bs[2][16][128+8];

    const int tid = threadIdx.x;
    const int m0 = blockIdx.y * BM, n0 = blockIdx.x * BM;
    const int tx = tid & 15, ty = tid >> 4;

    float4 aF[2], bF[2];

    #pragma unroll
    for (int i = 0; i < 2; i++) {
        int f = tid + i*256;
        int row = f >> 2, c4 = (f & 3) * 4;
        aF[i] = *(const float4*)&A[(size_t)(m0+row)*K + c4];
        bF[i] = *(const float4*)&B[(size_t)(n0+row)*K + c4];
    }
    #pragma unroll
    for (int i = 0; i < 2; i++) {
        int f = tid + i*256;
        int row = f >> 2, c4 = (f & 3) * 4;
        As[0][c4+0][row] = aF[i].x; As[0][c4+1][row] = aF[i].y;
        As[0][c4+2][row] = aF[i].z; As[0][c4+3][row] = aF[i].w;
        Bs[0][c4+0][row] = bF[i].x; Bs[0][c4+1][row] = bF[i].y;
        Bs[0][c4+2][row] = bF[i].z; Bs[0][c4+3][row] = bF[i].w;
    }
    __syncthreads();

    float acc[8][8];
    #pragma unroll
    for (int i = 0; i < 8; i++)
        #pragma unroll
        for (int j = 0; j < 8; j++) acc[i][j] = 0.f;

    const int nk = K / BK;
    for (int kt = 0; kt < nk; kt++) {
        const int cur = kt & 1;
        if (kt + 1 < nk) {
            int k0 = (kt+1)*BK;
            #pragma unroll
            for (int i = 0; i < 2; i++) {
                int f = tid + i*256;
                int row = f >> 2, c4 = (f & 3) * 4;
                aF[i] = *(const float4*)&A[(size_t)(m0+row)*K + k0 + c4];
                bF[i] = *(const float4*)&B[(size_t)(n0+row)*K + k0 + c4];
            }
        }
        #pragma unroll
        for (int k = 0; k < BK; k++) {
            float a[8], b[8];
            *(float4*)&a[0] = *(const float4*)&As[cur][k][ty*8];
            *(float4*)&a[4] = *(const float4*)&As[cur][k][ty*8+4];
            *(float4*)&b[0] = *(const float4*)&Bs[cur][k][tx*8];
            *(float4*)&b[4] = *(const float4*)&Bs[cur][k][tx*8+4];
            #pragma unroll
            for (int i = 0; i < 8; i++)
                #pragma unroll
                for (int j = 0; j < 8; j++)
                    acc[i][j] += a[i] * b[j];
        }
        if (kt + 1 < nk) {
            const int nxt = cur ^ 1;
            #pragma unroll
            for (int i = 0; i < 2; i++) {
                int f = tid + i*256;
                int row = f >> 2, c4 = (f & 3) * 4;
                As[nxt][c4+0][row] = aF[i].x; As[nxt][c4+1][row] = aF[i].y;
                As[nxt][c4+2][row] = aF[i].z; As[nxt][c4+3][row] = aF[i].w;
                Bs[nxt][c4+0][row] = bF[i].x; Bs[nxt][c4+1][row] = bF[i].y;
                Bs[nxt][c4+2][row] = bF[i].z; Bs[nxt][c4+3][row] = bF[i].w;
            }
            __syncthreads();
        }
    }

    #pragma unroll
    for (int i = 0; i < 8; i++) {
        int m = m0 + ty*8 + i;
        float bm = biasM ? biasM[m] : 0.f;
        #pragma unroll
        for (int j = 0; j < 8; j++) {
            int n = n0 + tx*8 + j;
            float v = acc[i][j] + bm;
            if (biasN) v += biasN[n];
            if (addMN) v += addMN[(size_t)m*N + n];
            if (do_silu) v = v / (1.f + __expf(-v));
            C[(size_t)m*N + n] = v;
        }
    }
}

// ---------------------------------------------------------------------------
// fp16 tensor-core GEMM for R:  C[16384,4096] = A[16384,1024] @ B[4096,1024]^T + biasM
// NT GEMM, both operands k-major -> BOTH sides use NON-TRANS ldmatrix.
// ---------------------------------------------------------------------------
#define RLD 40    // padded halves per SMEM row

__global__ __launch_bounds__(256, 2)
void gemm_r_fp16(const __half* __restrict__ A,
                 const __half* __restrict__ B,
                 const float* __restrict__ biasM,
                 float* __restrict__ C)
{
    __shared__ __align__(16) unsigned short As[2][128*RLD];
    __shared__ __align__(16) unsigned short Bs[2][64*RLD];

    const int tid = threadIdx.x;
    const int m0 = blockIdx.y * 128;
    const int n0 = blockIdx.x * 64;
    const int w  = tid >> 5, lane = tid & 31;
    const int wm = (w & 3) * 32;
    const int wn = (w >> 2) * 32;

    const int ar0 = tid >> 2,          ac = (tid & 3) * 8;
    const int ar1 = (tid >> 2) + 64;
    const int br  = tid >> 2;

    const __half* Ag = A + (size_t)m0*DIM;
    const __half* Bg = B + (size_t)n0*DIM;

    uint4 aR0 = *(const uint4*)(Ag + (size_t)ar0*DIM + ac);
    uint4 aR1 = *(const uint4*)(Ag + (size_t)ar1*DIM + ac);
    uint4 bR  = *(const uint4*)(Bg + (size_t)br *DIM + ac);
    *(uint4*)&As[0][ar0*RLD + ac] = aR0;
    *(uint4*)&As[0][ar1*RLD + ac] = aR1;
    *(uint4*)&Bs[0][br *RLD + ac] = bR;
    __syncthreads();

    float acc[2][4][4];
    #pragma unroll
    for (int tm = 0; tm < 2; tm++)
        #pragma unroll
        for (int tn = 0; tn < 4; tn++)
            #pragma unroll
            for (int e = 0; e < 4; e++) acc[tm][tn][e] = 0.f;

    const uint32_t aoff = ((uint32_t)(wm + (lane & 15)) * RLD + (lane >> 4) * 8) * 2;
    const uint32_t boff = ((uint32_t)(wn + (lane & 7))  * RLD + ((lane >> 3) & 1) * 8) * 2;
    const uint32_t aSm0 = (uint32_t)__cvta_generic_to_shared(&As[0][0]);
    const uint32_t bSm0 = (uint32_t)__cvta_generic_to_shared(&Bs[0][0]);
    const uint32_t aBufStride = 128*RLD*2;
    const uint32_t bBufStride = 64*RLD*2;

    const int NKT = DIM / 32;
    for (int kt = 0; kt < NKT; kt++) {
        const int cur = kt & 1;
        if (kt + 1 < NKT) {
            int k0 = (kt + 1) * 32;
            aR0 = *(const uint4*)(Ag + (size_t)ar0*DIM + k0 + ac);
            aR1 = *(const uint4*)(Ag + (size_t)ar1*DIM + k0 + ac);
            bR  = *(const uint4*)(Bg + (size_t)br *DIM + k0 + ac);
        }
        const uint32_t aB = aSm0 + cur * aBufStride;
        const uint32_t bB = bSm0 + cur * bBufStride;

        #pragma unroll
        for (int kh = 0; kh < 2; kh++) {
            uint32_t af[2][4];
            #pragma unroll
            for (int tm = 0; tm < 2; tm++) {
                uint32_t addr = aB + aoff + (uint32_t)(tm*16*RLD + kh*16) * 2;
                asm volatile(
                    "ldmatrix.sync.aligned.m8n8.x4.shared.b16 {%0,%1,%2,%3}, [%4];"
                    : "=r"(af[tm][0]), "=r"(af[tm][1]),
                      "=r"(af[tm][2]), "=r"(af[tm][3]) : "r"(addr));
            }
            uint32_t bf[4][2];
            #pragma unroll
            for (int tn = 0; tn < 4; tn++) {
                uint32_t addr = bB + boff + (uint32_t)(tn*8*RLD + kh*16) * 2;
                asm volatile(
                    "ldmatrix.sync.aligned.m8n8.x2.shared.b16 {%0,%1}, [%2];"
                    : "=r"(bf[tn][0]), "=r"(bf[tn][1]) : "r"(addr));
            }
            #pragma unroll
            for (int tm = 0; tm < 2; tm++)
                #pragma unroll
                for (int tn = 0; tn < 4; tn++) {
                    asm volatile(
                        "mma.sync.aligned.m16n8k16.row.col.f32.f16.f16.f32 "
                        "{%0,%1,%2,%3}, {%4,%5,%6,%7}, {%8,%9}, {%0,%1,%2,%3};"
                        : "+f"(acc[tm][tn][0]), "+f"(acc[tm][tn][1]),
                          "+f"(acc[tm][tn][2]), "+f"(acc[tm][tn][3])
                        : "r"(af[tm][0]), "r"(af[tm][1]),
                          "r"(af[tm][2]), "r"(af[tm][3]),
                          "r"(bf[tn][0]), "r"(bf[tn][1]));
                }
        }
        if (kt + 1 < NKT) {
            const int nxt = cur ^ 1;
            __syncthreads();
            *(uint4*)&As[nxt][ar0*RLD + ac] = aR0;
            *(uint4*)&As[nxt][ar1*RLD + ac] = aR1;
            *(uint4*)&Bs[nxt][br *RLD + ac] = bR;
            __syncthreads();
        }
    }

    const int gid = lane >> 2, tig = lane & 3;
    #pragma unroll
    for (int tm = 0; tm < 2; tm++) {
        int r0 = m0 + wm + tm*16 + gid;
        float bm0 = biasM[r0], bm8 = biasM[r0 + 8];
        #pragma unroll
        for (int tn = 0; tn < 4; tn++) {
            int col = n0 + wn + tn*8 + tig*2;
            float2 lo = make_float2(acc[tm][tn][0] + bm0, acc[tm][tn][1] + bm0);
            float2 hi = make_float2(acc[tm][tn][2] + bm8, acc[tm][tn][3] + bm8);
            *(float2*)&C[(size_t)r0*NSAMP + col]       = lo;
            *(float2*)&C[(size_t)(r0+8)*NSAMP + col]   = hi;
        }
    }
}

// ---------------------------------------------------------------------------
// Persistent sequential-scan kernel. 147 CTAs x 256 threads (8 warps).
// Warp w: gate wq = w>>1, K-half kh = w&1 (m8-blocks {2kh, 2kh+1}).
// Exchange: tagged-quad 441 fp32 slots (R12/R14 proven config), gpu-scope,
// sticky-fresh poll spread over 256 threads (<=2 slots each).
// Gates use hw tanh.approx.
// ---------------------------------------------------------------------------
#define SCAN_CTAS 147
#define SCAN_TPB  256
#define WS_HALFS  (LAYERS*28*1024)            // 114688 halves
#define WS_BYTES  (WS_HALFS*2)                // 229376 B
#define SCAN_SMEM (WS_BYTES + 2048 + (56+56)*4)   // + h_sm(fp16) + gpart[2][28] + ga[2][28]

__global__ __launch_bounds__(SCAN_TPB, 1)
void scan_kernel(const float* __restrict__ Whh, const float* __restrict__ R,
                 float* __restrict__ Hbuf)
{
    extern __shared__ unsigned char smem[];
    __half* ws    = (__half*)smem;                         // [(l*28+rl)*1024 + perm]
    __half* h_sm  = (__half*)(smem + WS_BYTES);            // [1024] permuted
    float*  gpart = (float*)(smem + WS_BYTES + 2048);      // [2][28] (kh-half partials)
    float*  ga    = gpart + 56;                            // [2][28]

    const int cta = blockIdx.x, tid = threadIdx.x;
    const int j0  = cta * 7;
    const int nj  = (j0 + 7 <= DIM) ? 7 : (DIM - j0);      // last CTA: 2

    // ---- fill SMEM weights (fp16, permuted: k = lane*32 + m8*8 + b at
    //      ws[row*1024 + m8*256 + lane*8 + b])
    for (int p = tid; p < WS_HALFS; p += SCAN_TPB) {
        int rowblk = p >> 10;                   // l*28 + rl
        int l  = rowblk / 28, rl = rowblk - l*28;
        int off = p & 1023;
        int m8 = off >> 8, ln = (off >> 3) & 31, b = off & 7;
        int q = rl / 7, u = rl - q*7;
        float v = 0.f;
        if (u < nj) {
            int k = ln*32 + m8*8 + b;
            v = Whh[((size_t)l*4*DIM + q*DIM + j0 + u)*DIM + k];
        }
        ws[p] = __float2half(v);
    }
    __syncthreads();

    const int w = tid >> 5, lane = tid & 31;
    const int wq = w >> 1;          // gate index 0..3
    const int kh = w & 1;           // m8-half: m8 in {2kh, 2kh+1}
    float cst = 0.f;                // c state (warp0 lanes < 7)

    // ---- per-thread poll-slot assignment (<=2 slots over 256 threads)
    int nsl = 0;
    int sid2[2], jb2[2], dm2[2];
    #pragma unroll
    for (int k = 0; k < 2; k++) {
        int s = tid + 256*k;
        if (s < NSLOT) {
            int cs = s / 3, r = s - 3*cs;
            int jb = cs*7 + r*3;
            if (jb < DIM) {
                int njc = (cs*7 + 7 <= DIM) ? 7 : (DIM - cs*7);
                int dm = njc - r*3; if (dm > 3) dm = 3;
                if (dm > 0) { sid2[nsl] = s; jb2[nsl] = jb; dm2[nsl] = dm; nsl++; }
            }
        }
    }

    // ---- R prefetch bookkeeping (one step ahead), threads 0..27
    int pf_q = 0, pf_u = 0;
    bool pf_act = (tid < 28);
    if (pf_act) { pf_q = tid / 7; pf_u = tid - pf_q*7; pf_act = (pf_u < nj); }
    float a_cur = 0.f;
    if (pf_act)   // step g=1: i=0, l=0
        a_cur = R[((size_t)(pf_q*DIM + j0 + pf_u))*NSAMP + 0];

    #pragma unroll 1
    for (int g = 1; g <= NSTEP; ++g) {
        const int s = g - 1;
        const int i = s >> 2, l = s & 3;

        float a_nxt = 0.f;
        if (pf_act && g < NSTEP) {
            int i2 = g >> 2, l2 = g & 3;
            a_nxt = R[((size_t)(l2*4*DIM + pf_q*DIM + j0 + pf_u))*NSAMP + i2];
        }
        if (tid < 28) ga[(g & 1)*28 + tid] = a_cur;

        // ---- tagged-quad poll (sticky per-slot freshness)
        {
            const uint4* hb = g_hx + ((s & 1) * NSLOT);
            const unsigned want = (unsigned)s;     // accept tag >= s
            uint4 vv[2];
            unsigned fresh = 0;
            const unsigned all = (1u << nsl) - 1u;
            do {
                #pragma unroll
                for (int k = 0; k < 2; k++) if (k < nsl) {
                    if (!(fresh & (1u << k))) {
                        vv[k] = ldv4(hb + sid2[k]);
                        if (vv[k].w >= want) fresh |= (1u << k);
                    }
                }
            } while (fresh != all);
            #pragma unroll
            for (int k = 0; k < 2; k++) if (k < nsl) {
                unsigned dat[3] = { vv[k].x, vv[k].y, vv[k].z };
                #pragma unroll
                for (int d = 0; d < 3; d++) if (d < dm2[k]) {
                    int j = jb2[k] + d;
                    int p = ((j >> 3) & 3)*256 + (j >> 5)*8 + (j & 7);
                    h_sm[p] = __float2half(__uint_as_float(dat[d]));
                }
            }
        }
        __syncthreads();   // B1

        // ---- load this warp's h half (m8 = 2kh, 2kh+1) as half2
        __half2 hh[8];
        *(uint4*)&hh[0] = *(const uint4*)&h_sm[(2*kh    )*256 + lane*8];
        *(uint4*)&hh[4] = *(const uint4*)&h_sm[(2*kh + 1)*256 + lane*8];

        // ---- 7 rows (gate wq) over this half: HFMA2 chains of 2 + fp32 flush
        const __half2 hz = __float2half2_rn(0.f);
        float part[7];
        #pragma unroll
        for (int t = 0; t < 7; t++) {
            const int rl = wq*7 + t;
            const __half* wr = ws + (((size_t)l*28 + rl) << 10);
            uint4 wv0 = *(const uint4*)&wr[(2*kh    )*256 + lane*8];
            uint4 wv1 = *(const uint4*)&wr[(2*kh + 1)*256 + lane*8];
            const __half2* wa = (const __half2*)&wv0;
            const __half2* wb = (const __half2*)&wv1;
            __half2 ac0 = hz, ac1 = hz, ac2 = hz, ac3 = hz;
            ac0 = __hfma2(wa[0], hh[0], ac0);
            ac1 = __hfma2(wa[1], hh[1], ac1);
            ac2 = __hfma2(wa[2], hh[2], ac2);
            ac3 = __hfma2(wa[3], hh[3], ac3);
            ac0 = __hfma2(wb[0], hh[4], ac0);
            ac1 = __hfma2(wb[1], hh[5], ac1);
            ac2 = __hfma2(wb[2], hh[6], ac2);
            ac3 = __hfma2(wb[3], hh[7], ac3);
            float2 f0 = __half22float2(ac0);
            float2 f1 = __half22float2(ac1);
            float2 f2 = __half22float2(ac2);
            float2 f3 = __half22float2(ac3);
            part[t] = (f0.x + f0.y) + (f1.x + f1.y)
                    + (f2.x + f2.y) + (f3.x + f3.y);
        }
        #pragma unroll
        for (int t = 0; t < 7; t++) {
            float v = part[t];
            v += __shfl_xor_sync(0xffffffffu, v, 16);
            v += __shfl_xor_sync(0xffffffffu, v, 8);
            v += __shfl_xor_sync(0xffffffffu, v, 4);
            v += __shfl_xor_sync(0xffffffffu, v, 2);
            v += __shfl_xor_sync(0xffffffffu, v, 1);
            if (lane == 0) gpart[kh*28 + wq*7 + t] = v;
        }
        __syncthreads();   // B2

        // ---- gates (hw tanh) + tagged-quad publish (warp 0)
        if (w == 0) {
            float h = 0.f;
            if (lane < nj) {
                const float* gav = ga + (g & 1)*28;
                float gi = gpart[lane]      + gpart[28 + lane]      + gav[lane];
                float gf = gpart[7 + lane]  + gpart[28 + 7 + lane]  + gav[7 + lane];
                float gg = gpart[14 + lane] + gpart[28 + 14 + lane] + gav[14 + lane];
                float go = gpart[21 + lane] + gpart[28 + 21 + lane] + gav[21 + lane];
                float I = sigmoid_hw(gi);
                float F = sigmoid_hw(gf);
                float G = tanh_hw(gg);
                cst = F * cst + I * G;
                float O = sigmoid_hw(go);
                h = O * tanh_hw(cst);
            }
            float p0 = __shfl_sync(0xffffffffu, h, (3*lane)     & 31);
            float p1 = __shfl_sync(0xffffffffu, h, (3*lane + 1) & 31);
            float p2 = __shfl_sync(0xffffffffu, h, (3*lane + 2) & 31);
            if (lane < 3 && 3*lane < nj) {
                uint4 pk;
                pk.x = __float_as_uint(p0);
                pk.y = __float_as_uint(p1);
                pk.z = __float_as_uint(p2);
                pk.w = (unsigned)g;
                stv4(&g_hx[(g & 1)*NSLOT + cta*3 + lane], pk);
            }
            if (lane < nj && l == 3)
                Hbuf[(size_t)i*DIM + j0 + lane] = h;
        }
        a_cur = a_nxt;
        // no trailing barrier: next step's poll self-synchronizes on tags
    }
}

// ---------------------------------------------------------------------------
// Launch
// ---------------------------------------------------------------------------
extern "C" void kernel_launch(void* const* d_in, const int* in_sizes, int n_in,
                              void* d_out, int out_size)
{
    const float* x      = (const float*)d_in[0];
    const int*   ts     = (const int*)  d_in[1];
    const float* proj_w = (const float*)d_in[2];
    const float* proj_b = (const float*)d_in[3];
    const float* te_w1  = (const float*)d_in[4];
    const float* te_b1  = (const float*)d_in[5];
    const float* te_w2  = (const float*)d_in[6];
    const float* te_b2  = (const float*)d_in[7];
    const float* Wih    = (const float*)d_in[8];
    const float* Whh    = (const float*)d_in[9];
    const float* bih    = (const float*)d_in[10];
    const float* bhh    = (const float*)d_in[11];
    const float* lin_w  = (const float*)d_in[12];
    const float* lin_b  = (const float*)d_in[13];
    float* out = (float*)d_out;

    float *PE, *T1, *EMB, *XP, *R, *H, *BS;
    __half *WihH, *XPH;
    cudaGetSymbolAddress((void**)&PE,  g_PE);
    cudaGetSymbolAddress((void**)&T1,  g_T1);
    cudaGetSymbolAddress((void**)&EMB, g_EMB);
    cudaGetSymbolAddress((void**)&XP,  g_XP);
    cudaGetSymbolAddress((void**)&R,   g_R);
    cudaGetSymbolAddress((void**)&H,   g_H);
    cudaGetSymbolAddress((void**)&BS,  g_BS);
    cudaGetSymbolAddress((void**)&WihH, g_WihH);
    cudaGetSymbolAddress((void**)&XPH,  g_XPH);

    cudaFuncSetAttribute(scan_kernel, cudaFuncAttributeMaxDynamicSharedMemorySize,
                         SCAN_SMEM);

    // 1) sinusoidal PE
    pe_kernel<<<NSAMP, 128>>>(ts, PE);
    // 2) T1 = silu(PE @ te_w1^T + te_b1)
    gemm_nt<<<dim3(DIM/128, NSAMP/128), 256>>>(PE, te_w1, T1, NSAMP, DIM, DIM,
                                               nullptr, te_b1, nullptr, 1);
    // 3) EMB = T1 @ te_w2^T + te_b2
    gemm_nt<<<dim3(DIM/128, NSAMP/128), 256>>>(T1, te_w2, EMB, NSAMP, DIM, DIM,
                                               nullptr, te_b2, nullptr, 0);
    // 4) XP = x @ proj_w^T + proj_b + EMB
    gemm_nt<<<dim3(DIM/128, NSAMP/128), 256>>>(x, proj_w, XP, NSAMP, DIM, DIM,
                                               nullptr, proj_b, EMB, 0);
    // 5) stacked gate bias
    bias_kernel<<<GROWS/256, 256>>>(bih, bhh, BS);
    // 6) fp16 conversions for the tensor-core R GEMM
    conv_fp16_kernel<<<((GROWS*DIM/4)+255)/256, 256>>>(Wih, WihH, GROWS*DIM/4);
    conv_fp16_kernel<<<((NSAMP*DIM/4)+255)/256, 256>>>(XP, XPH, NSAMP*DIM/4);
    // 7) R = Wih_stack @ XP^T + bias   (16384 x 4096 x 1024) — fp16 HMMA
    gemm_r_fp16<<<dim3(NSAMP/64, GROWS/128), 256>>>(WihH, XPH, BS, R);
    // 8) reset tagged h slots (graph-replay safe)
    reset_kernel<<<(2*NSLOT+255)/256, 256>>>();
    // 9) persistent sequential scan
    scan_kernel<<<SCAN_CTAS, SCAN_TPB, SCAN_SMEM>>>(Whh, R, H);
    // 10) out = H @ lin_w^T + lin_b (fp32 — output precision)
    gemm_nt<<<dim3(DIM/128, NSAMP/128), 256>>>(H, lin_w, out, NSAMP, DIM, DIM,
                                               nullptr, lin_b, nullptr, 0);
}

// round 17
// speedup vs baseline: 1.3769x; 1.0370x over previous
#include <cuda_runtime.h>
#include <cuda_fp16.h>
#include <cstdint>

// ---------------------------------------------------------------------------
// Problem constants
// ---------------------------------------------------------------------------
#define NSAMP 4096
#define DIM   1024     // IN == HID == DIM_T
#define LAYERS 4
#define GROWS (LAYERS*4*DIM)       // 16384 stacked gate rows
#define NSTEP (NSAMP*LAYERS)       // 16384 sequential steps
#define NSLOT 441                  // 147 CTAs * 3 slots (3 h values + tag each)

// ---------------------------------------------------------------------------
// Scratch (static device globals; no runtime allocation)
// ---------------------------------------------------------------------------
__device__ __half g_PEH [(size_t)NSAMP*DIM];
__device__ __half g_xH  [(size_t)NSAMP*DIM];
__device__ __half g_T1H [(size_t)NSAMP*DIM];
__device__ __half g_EMBH[(size_t)NSAMP*DIM];
__device__ __half g_XPH [(size_t)NSAMP*DIM];
__device__ __half g_tw1H[(size_t)DIM*DIM];
__device__ __half g_tw2H[(size_t)DIM*DIM];
__device__ __half g_pwH [(size_t)DIM*DIM];
__device__ __half g_WihH[(size_t)GROWS*DIM];   // 32 MB fp16 Wih
__device__ float g_R  [(size_t)GROWS*NSAMP];   // 256 MB: R[row, i]
__device__ float g_H  [(size_t)NSAMP*DIM];
__device__ float g_BS [GROWS];
// Tagged-quad h exchange, double-buffered by step parity.
// Slot = {h0,h1,h2, tag}. Buffer b holds steps with (g&1)==b.
__device__ uint4 g_hx[2*NSLOT];

// ---------------------------------------------------------------------------
// 16B GPU-scope vector ld/st (performed at L2; no SYS/C2C coherence cost)
// ---------------------------------------------------------------------------
__device__ __forceinline__ uint4 ldv4(const uint4* p) {
    uint4 v;
    asm volatile("ld.relaxed.gpu.global.v4.u32 {%0,%1,%2,%3}, [%4];"
                 : "=r"(v.x), "=r"(v.y), "=r"(v.z), "=r"(v.w) : "l"(p) : "memory");
    return v;
}
__device__ __forceinline__ void stv4(uint4* p, uint4 v) {
    asm volatile("st.relaxed.gpu.global.v4.u32 [%0], {%1,%2,%3,%4};"
                 :: "l"(p), "r"(v.x), "r"(v.y), "r"(v.z), "r"(v.w) : "memory");
}

__device__ __forceinline__ float tanh_hw(float x) {
    float y;
    asm("tanh.approx.f32 %0, %1;" : "=f"(y) : "f"(x));
    return y;
}
__device__ __forceinline__ float sigmoid_hw(float x) {
    return 0.5f + 0.5f * tanh_hw(0.5f * x);
}

// ---------------------------------------------------------------------------
// Small prologue kernels
// ---------------------------------------------------------------------------
__global__ void pe_kernel(const int* __restrict__ ts, __half* __restrict__ PE) {
    int i = blockIdx.x;
    float t = (float)ts[i];
    for (int d = threadIdx.x; d < DIM/2; d += blockDim.x) {
        float f = expf((float)d * (-9.210340371976184f / (float)(DIM/2 - 1)));
        float a = t * f;
        PE[(size_t)i*DIM + d]          = __float2half(sinf(a));
        PE[(size_t)i*DIM + DIM/2 + d]  = __float2half(cosf(a));
    }
}

__global__ void bias_kernel(const float* __restrict__ bih, const float* __restrict__ bhh,
                            float* __restrict__ out) {
    int idx = blockIdx.x*blockDim.x + threadIdx.x;
    if (idx < GROWS) out[idx] = bih[idx] + bhh[idx];
}

__global__ void reset_kernel() {
    int idx = blockIdx.x*blockDim.x + threadIdx.x;
    if (idx < 2*NSLOT) g_hx[idx] = make_uint4(0u, 0u, 0u, 0u);  // tag 0, h = 0
}

__global__ void conv_fp16_kernel(const float* __restrict__ src,
                                 __half* __restrict__ dst, int n4) {
    int i = blockIdx.x*blockDim.x + threadIdx.x;
    if (i < n4) {
        float4 v = *(const float4*)&src[(size_t)i*4];
        __half o[4];
        o[0] = __float2half_rn(v.x);
        o[1] = __float2half_rn(v.y);
        o[2] = __float2half_rn(v.z);
        o[3] = __float2half_rn(v.w);
        *(uint2*)&dst[(size_t)i*4] = *(uint2*)o;
    }
}

// ---------------------------------------------------------------------------
// Generic NT GEMM (fp32 SIMT) — used only for the output GEMM (precision).
// ---------------------------------------------------------------------------
__global__ __launch_bounds__(256, 2)
void gemm_nt(const float* __restrict__ A, const float* __restrict__ B,
             float* __restrict__ C, int M, int N, int K,
             const float* __restrict__ biasM, const float* __restrict__ biasN,
             const float* __restrict__ addMN, int do_silu)
{
    const int BM = 128, BK = 16;
    __shared__ float As[2][16][128+8];
    __shared__ float Bs[2][16][128+8];

    const int tid = threadIdx.x;
    const int m0 = blockIdx.y * BM, n0 = blockIdx.x * BM;
    const int tx = tid & 15, ty = tid >> 4;

    float4 aF[2], bF[2];

    #pragma unroll
    for (int i = 0; i < 2; i++) {
        int f = tid + i*256;
        int row = f >> 2, c4 = (f & 3) * 4;
        aF[i] = *(const float4*)&A[(size_t)(m0+row)*K + c4];
        bF[i] = *(const float4*)&B[(size_t)(n0+row)*K + c4];
    }
    #pragma unroll
    for (int i = 0; i < 2; i++) {
        int f = tid + i*256;
        int row = f >> 2, c4 = (f & 3) * 4;
        As[0][c4+0][row] = aF[i].x; As[0][c4+1][row] = aF[i].y;
        As[0][c4+2][row] = aF[i].z; As[0][c4+3][row] = aF[i].w;
        Bs[0][c4+0][row] = bF[i].x; Bs[0][c4+1][row] = bF[i].y;
        Bs[0][c4+2][row] = bF[i].z; Bs[0][c4+3][row] = bF[i].w;
    }
    __syncthreads();

    float acc[8][8];
    #pragma unroll
    for (int i = 0; i < 8; i++)
        #pragma unroll
        for (int j = 0; j < 8; j++) acc[i][j] = 0.f;

    const int nk = K / BK;
    for (int kt = 0; kt < nk; kt++) {
        const int cur = kt & 1;
        if (kt + 1 < nk) {
            int k0 = (kt+1)*BK;
            #pragma unroll
            for (int i = 0; i < 2; i++) {
                int f = tid + i*256;
                int row = f >> 2, c4 = (f & 3) * 4;
                aF[i] = *(const float4*)&A[(size_t)(m0+row)*K + k0 + c4];
                bF[i] = *(const float4*)&B[(size_t)(n0+row)*K + k0 + c4];
            }
        }
        #pragma unroll
        for (int k = 0; k < BK; k++) {
            float a[8], b[8];
            *(float4*)&a[0] = *(const float4*)&As[cur][k][ty*8];
            *(float4*)&a[4] = *(const float4*)&As[cur][k][ty*8+4];
            *(float4*)&b[0] = *(const float4*)&Bs[cur][k][tx*8];
            *(float4*)&b[4] = *(const float4*)&Bs[cur][k][tx*8+4];
            #pragma unroll
            for (int i = 0; i < 8; i++)
                #pragma unroll
                for (int j = 0; j < 8; j++)
                    acc[i][j] += a[i] * b[j];
        }
        if (kt + 1 < nk) {
            const int nxt = cur ^ 1;
            #pragma unroll
            for (int i = 0; i < 2; i++) {
                int f = tid + i*256;
                int row = f >> 2, c4 = (f & 3) * 4;
                As[nxt][c4+0][row] = aF[i].x; As[nxt][c4+1][row] = aF[i].y;
                As[nxt][c4+2][row] = aF[i].z; As[nxt][c4+3][row] = aF[i].w;
                Bs[nxt][c4+0][row] = bF[i].x; Bs[nxt][c4+1][row] = bF[i].y;
                Bs[nxt][c4+2][row] = bF[i].z; Bs[nxt][c4+3][row] = bF[i].w;
            }
            __syncthreads();
        }
    }

    #pragma unroll
    for (int i = 0; i < 8; i++) {
        int m = m0 + ty*8 + i;
        float bm = biasM ? biasM[m] : 0.f;
        #pragma unroll
        for (int j = 0; j < 8; j++) {
            int n = n0 + tx*8 + j;
            float v = acc[i][j] + bm;
            if (biasN) v += biasN[n];
            if (addMN) v += addMN[(size_t)m*N + n];
            if (do_silu) v = v / (1.f + __expf(-v));
            C[(size_t)m*N + n] = v;
        }
    }
}

// ---------------------------------------------------------------------------
// fp16 HMMA NT GEMM core (BM=128, BN=64, BK=32, 8 warps, non-trans ldmatrix).
// Two instantiations: gemm_r_fp16 (fp32 out, biasM) and gemm_h16 (fp16 out,
// biasN + optional fp16 add + optional silu) for the prologue chain.
// ---------------------------------------------------------------------------
#define RLD 40    // padded halves per SMEM row

__global__ __launch_bounds__(256, 2)
void gemm_r_fp16(const __half* __restrict__ A,
                 const __half* __restrict__ B,
                 const float* __restrict__ biasM,
                 float* __restrict__ C)
{
    __shared__ __align__(16) unsigned short As[2][128*RLD];
    __shared__ __align__(16) unsigned short Bs[2][64*RLD];

    const int tid = threadIdx.x;
    const int m0 = blockIdx.y * 128;
    const int n0 = blockIdx.x * 64;
    const int w  = tid >> 5, lane = tid & 31;
    const int wm = (w & 3) * 32;
    const int wn = (w >> 2) * 32;

    const int ar0 = tid >> 2,          ac = (tid & 3) * 8;
    const int ar1 = (tid >> 2) + 64;
    const int br  = tid >> 2;

    const __half* Ag = A + (size_t)m0*DIM;
    const __half* Bg = B + (size_t)n0*DIM;

    uint4 aR0 = *(const uint4*)(Ag + (size_t)ar0*DIM + ac);
    uint4 aR1 = *(const uint4*)(Ag + (size_t)ar1*DIM + ac);
    uint4 bR  = *(const uint4*)(Bg + (size_t)br *DIM + ac);
    *(uint4*)&As[0][ar0*RLD + ac] = aR0;
    *(uint4*)&As[0][ar1*RLD + ac] = aR1;
    *(uint4*)&Bs[0][br *RLD + ac] = bR;
    __syncthreads();

    float acc[2][4][4];
    #pragma unroll
    for (int tm = 0; tm < 2; tm++)
        #pragma unroll
        for (int tn = 0; tn < 4; tn++)
            #pragma unroll
            for (int e = 0; e < 4; e++) acc[tm][tn][e] = 0.f;

    const uint32_t aoff = ((uint32_t)(wm + (lane & 15)) * RLD + (lane >> 4) * 8) * 2;
    const uint32_t boff = ((uint32_t)(wn + (lane & 7))  * RLD + ((lane >> 3) & 1) * 8) * 2;
    const uint32_t aSm0 = (uint32_t)__cvta_generic_to_shared(&As[0][0]);
    const uint32_t bSm0 = (uint32_t)__cvta_generic_to_shared(&Bs[0][0]);
    const uint32_t aBufStride = 128*RLD*2;
    const uint32_t bBufStride = 64*RLD*2;

    const int NKT = DIM / 32;
    for (int kt = 0; kt < NKT; kt++) {
        const int cur = kt & 1;
        if (kt + 1 < NKT) {
            int k0 = (kt + 1) * 32;
            aR0 = *(const uint4*)(Ag + (size_t)ar0*DIM + k0 + ac);
            aR1 = *(const uint4*)(Ag + (size_t)ar1*DIM + k0 + ac);
            bR  = *(const uint4*)(Bg + (size_t)br *DIM + k0 + ac);
        }
        const uint32_t aB = aSm0 + cur * aBufStride;
        const uint32_t bB = bSm0 + cur * bBufStride;

        #pragma unroll
        for (int kh = 0; kh < 2; kh++) {
            uint32_t af[2][4];
            #pragma unroll
            for (int tm = 0; tm < 2; tm++) {
                uint32_t addr = aB + aoff + (uint32_t)(tm*16*RLD + kh*16) * 2;
                asm volatile(
                    "ldmatrix.sync.aligned.m8n8.x4.shared.b16 {%0,%1,%2,%3}, [%4];"
                    : "=r"(af[tm][0]), "=r"(af[tm][1]),
                      "=r"(af[tm][2]), "=r"(af[tm][3]) : "r"(addr));
            }
            uint32_t bf[4][2];
            #pragma unroll
            for (int tn = 0; tn < 4; tn++) {
                uint32_t addr = bB + boff + (uint32_t)(tn*8*RLD + kh*16) * 2;
                asm volatile(
                    "ldmatrix.sync.aligned.m8n8.x2.shared.b16 {%0,%1}, [%2];"
                    : "=r"(bf[tn][0]), "=r"(bf[tn][1]) : "r"(addr));
            }
            #pragma unroll
            for (int tm = 0; tm < 2; tm++)
                #pragma unroll
                for (int tn = 0; tn < 4; tn++) {
                    asm volatile(
                        "mma.sync.aligned.m16n8k16.row.col.f32.f16.f16.f32 "
                        "{%0,%1,%2,%3}, {%4,%5,%6,%7}, {%8,%9}, {%0,%1,%2,%3};"
                        : "+f"(acc[tm][tn][0]), "+f"(acc[tm][tn][1]),
                          "+f"(acc[tm][tn][2]), "+f"(acc[tm][tn][3])
                        : "r"(af[tm][0]), "r"(af[tm][1]),
                          "r"(af[tm][2]), "r"(af[tm][3]),
                          "r"(bf[tn][0]), "r"(bf[tn][1]));
                }
        }
        if (kt + 1 < NKT) {
            const int nxt = cur ^ 1;
            __syncthreads();
            *(uint4*)&As[nxt][ar0*RLD + ac] = aR0;
            *(uint4*)&As[nxt][ar1*RLD + ac] = aR1;
            *(uint4*)&Bs[nxt][br *RLD + ac] = bR;
            __syncthreads();
        }
    }

    const int gid = lane >> 2, tig = lane & 3;
    #pragma unroll
    for (int tm = 0; tm < 2; tm++) {
        int r0 = m0 + wm + tm*16 + gid;
        float bm0 = biasM[r0], bm8 = biasM[r0 + 8];
        #pragma unroll
        for (int tn = 0; tn < 4; tn++) {
            int col = n0 + wn + tn*8 + tig*2;
            float2 lo = make_float2(acc[tm][tn][0] + bm0, acc[tm][tn][1] + bm0);
            float2 hi = make_float2(acc[tm][tn][2] + bm8, acc[tm][tn][3] + bm8);
            *(float2*)&C[(size_t)r0*NSAMP + col]       = lo;
            *(float2*)&C[(size_t)(r0+8)*NSAMP + col]   = hi;
        }
    }
}

// fp16-out HMMA GEMM: C[m,n] = A[m,:]·B[n,:] + biasN[n] (+addMN[m,n]) (silu)
// M rows from grid.y*128, N = DIM output cols, K = DIM.
__global__ __launch_bounds__(256, 2)
void gemm_h16(const __half* __restrict__ A,
              const __half* __restrict__ B,
              __half* __restrict__ C,
              const float* __restrict__ biasN,
              const __half* __restrict__ addMN,
              int do_silu)
{
    __shared__ __align__(16) unsigned short As[2][128*RLD];
    __shared__ __align__(16) unsigned short Bs[2][64*RLD];

    const int tid = threadIdx.x;
    const int m0 = blockIdx.y * 128;
    const int n0 = blockIdx.x * 64;
    const int w  = tid >> 5, lane = tid & 31;
    const int wm = (w & 3) * 32;
    const int wn = (w >> 2) * 32;

    const int ar0 = tid >> 2,          ac = (tid & 3) * 8;
    const int ar1 = (tid >> 2) + 64;
    const int br  = tid >> 2;

    const __half* Ag = A + (size_t)m0*DIM;
    const __half* Bg = B + (size_t)n0*DIM;

    uint4 aR0 = *(const uint4*)(Ag + (size_t)ar0*DIM + ac);
    uint4 aR1 = *(const uint4*)(Ag + (size_t)ar1*DIM + ac);
    uint4 bR  = *(const uint4*)(Bg + (size_t)br *DIM + ac);
    *(uint4*)&As[0][ar0*RLD + ac] = aR0;
    *(uint4*)&As[0][ar1*RLD + ac] = aR1;
    *(uint4*)&Bs[0][br *RLD + ac] = bR;
    __syncthreads();

    float acc[2][4][4];
    #pragma unroll
    for (int tm = 0; tm < 2; tm++)
        #pragma unroll
        for (int tn = 0; tn < 4; tn++)
            #pragma unroll
            for (int e = 0; e < 4; e++) acc[tm][tn][e] = 0.f;

    const uint32_t aoff = ((uint32_t)(wm + (lane & 15)) * RLD + (lane >> 4) * 8) * 2;
    const uint32_t boff = ((uint32_t)(wn + (lane & 7))  * RLD + ((lane >> 3) & 1) * 8) * 2;
    const uint32_t aSm0 = (uint32_t)__cvta_generic_to_shared(&As[0][0]);
    const uint32_t bSm0 = (uint32_t)__cvta_generic_to_shared(&Bs[0][0]);
    const uint32_t aBufStride = 128*RLD*2;
    const uint32_t bBufStride = 64*RLD*2;

    const int NKT = DIM / 32;
    for (int kt = 0; kt < NKT; kt++) {
        const int cur = kt & 1;
        if (kt + 1 < NKT) {
            int k0 = (kt + 1) * 32;
            aR0 = *(const uint4*)(Ag + (size_t)ar0*DIM + k0 + ac);
            aR1 = *(const uint4*)(Ag + (size_t)ar1*DIM + k0 + ac);
            bR  = *(const uint4*)(Bg + (size_t)br *DIM + k0 + ac);
        }
        const uint32_t aB = aSm0 + cur * aBufStride;
        const uint32_t bB = bSm0 + cur * bBufStride;

        #pragma unroll
        for (int kh = 0; kh < 2; kh++) {
            uint32_t af[2][4];
            #pragma unroll
            for (int tm = 0; tm < 2; tm++) {
                uint32_t addr = aB + aoff + (uint32_t)(tm*16*RLD + kh*16) * 2;
                asm volatile(
                    "ldmatrix.sync.aligned.m8n8.x4.shared.b16 {%0,%1,%2,%3}, [%4];"
                    : "=r"(af[tm][0]), "=r"(af[tm][1]),
                      "=r"(af[tm][2]), "=r"(af[tm][3]) : "r"(addr));
            }
            uint32_t bf[4][2];
            #pragma unroll
            for (int tn = 0; tn < 4; tn++) {
                uint32_t addr = bB + boff + (uint32_t)(tn*8*RLD + kh*16) * 2;
                asm volatile(
                    "ldmatrix.sync.aligned.m8n8.x2.shared.b16 {%0,%1}, [%2];"
                    : "=r"(bf[tn][0]), "=r"(bf[tn][1]) : "r"(addr));
            }
            #pragma unroll
            for (int tm = 0; tm < 2; tm++)
                #pragma unroll
                for (int tn = 0; tn < 4; tn++) {
                    asm volatile(
                        "mma.sync.aligned.m16n8k16.row.col.f32.f16.f16.f32 "
                        "{%0,%1,%2,%3}, {%4,%5,%6,%7}, {%8,%9}, {%0,%1,%2,%3};"
                        : "+f"(acc[tm][tn][0]), "+f"(acc[tm][tn][1]),
                          "+f"(acc[tm][tn][2]), "+f"(acc[tm][tn][3])
                        : "r"(af[tm][0]), "r"(af[tm][1]),
                          "r"(af[tm][2]), "r"(af[tm][3]),
                          "r"(bf[tn][0]), "r"(bf[tn][1]));
                }
        }
        if (kt + 1 < NKT) {
            const int nxt = cur ^ 1;
            __syncthreads();
            *(uint4*)&As[nxt][ar0*RLD + ac] = aR0;
            *(uint4*)&As[nxt][ar1*RLD + ac] = aR1;
            *(uint4*)&Bs[nxt][br *RLD + ac] = bR;
            __syncthreads();
        }
    }

    const int gid = lane >> 2, tig = lane & 3;
    #pragma unroll
    for (int tm = 0; tm < 2; tm++) {
        int r0 = m0 + wm + tm*16 + gid;
        #pragma unroll
        for (int tn = 0; tn < 4; tn++) {
            int col = n0 + wn + tn*8 + tig*2;
            float bn0 = biasN[col], bn1 = biasN[col + 1];
            float v00 = acc[tm][tn][0] + bn0, v01 = acc[tm][tn][1] + bn1;
            float v10 = acc[tm][tn][2] + bn0, v11 = acc[tm][tn][3] + bn1;
            if (addMN) {
                float2 e0 = __half22float2(*(const __half2*)&addMN[(size_t)r0*DIM + col]);
                float2 e1 = __half22float2(*(const __half2*)&addMN[(size_t)(r0+8)*DIM + col]);
                v00 += e0.x; v01 += e0.y; v10 += e1.x; v11 += e1.y;
            }
            if (do_silu) {
                v00 = v00 / (1.f + __expf(-v00));
                v01 = v01 / (1.f + __expf(-v01));
                v10 = v10 / (1.f + __expf(-v10));
                v11 = v11 / (1.f + __expf(-v11));
            }
            *(__half2*)&C[(size_t)r0*DIM + col]     = __floats2half2_rn(v00, v01);
            *(__half2*)&C[(size_t)(r0+8)*DIM + col] = __floats2half2_rn(v10, v11);
        }
    }
}

// ---------------------------------------------------------------------------
// Persistent sequential-scan kernel. 147 CTAs x 256 threads (8 warps).
// Warp w: gate wq = w>>1, K-half kh = w&1 (m8-blocks {2kh, 2kh+1}).
// Exchange: tagged-quad 441 fp32 slots, gpu-scope, sticky-fresh poll.
// R16: weights prefetched into regs BEFORE the poll; HADD2-tree flush.
// ---------------------------------------------------------------------------
#define SCAN_CTAS 147
#define SCAN_TPB  256
#define WS_HALFS  (LAYERS*28*1024)            // 114688 halves
#define WS_BYTES  (WS_HALFS*2)                // 229376 B
#define SCAN_SMEM (WS_BYTES + 2048 + (56+56)*4)

__global__ __launch_bounds__(SCAN_TPB, 1)
void scan_kernel(const float* __restrict__ Whh, const float* __restrict__ R,
                 float* __restrict__ Hbuf)
{
    extern __shared__ unsigned char smem[];
    __half* ws    = (__half*)smem;                         // [(l*28+rl)*1024 + perm]
    __half* h_sm  = (__half*)(smem + WS_BYTES);            // [1024] permuted
    float*  gpart = (float*)(smem + WS_BYTES + 2048);      // [2][28]
    float*  ga    = gpart + 56;                            // [2][28]

    const int cta = blockIdx.x, tid = threadIdx.x;
    const int j0  = cta * 7;
    const int nj  = (j0 + 7 <= DIM) ? 7 : (DIM - j0);      // last CTA: 2

    for (int p = tid; p < WS_HALFS; p += SCAN_TPB) {
        int rowblk = p >> 10;                   // l*28 + rl
        int l  = rowblk / 28, rl = rowblk - l*28;
        int off = p & 1023;
        int m8 = off >> 8, ln = (off >> 3) & 31, b = off & 7;
        int q = rl / 7, u = rl - q*7;
        float v = 0.f;
        if (u < nj) {
            int k = ln*32 + m8*8 + b;
            v = Whh[((size_t)l*4*DIM + q*DIM + j0 + u)*DIM + k];
        }
        ws[p] = __float2half(v);
    }
    __syncthreads();

    const int w = tid >> 5, lane = tid & 31;
    const int wq = w >> 1;          // gate index 0..3
    const int kh = w & 1;           // m8-half: m8 in {2kh, 2kh+1}
    float cst = 0.f;                // c state (warp0 lanes < 7)

    // ---- per-thread poll-slot assignment (<=2 slots over 256 threads)
    int nsl = 0;
    int sid2[2], jb2[2], dm2[2];
    #pragma unroll
    for (int k = 0; k < 2; k++) {
        int s = tid + 256*k;
        if (s < NSLOT) {
            int cs = s / 3, r = s - 3*cs;
            int jb = cs*7 + r*3;
            if (jb < DIM) {
                int njc = (cs*7 + 7 <= DIM) ? 7 : (DIM - cs*7);
                int dm = njc - r*3; if (dm > 3) dm = 3;
                if (dm > 0) { sid2[nsl] = s; jb2[nsl] = jb; dm2[nsl] = dm; nsl++; }
            }
        }
    }

    // ---- R prefetch bookkeeping (one step ahead), threads 0..27
    int pf_q = 0, pf_u = 0;
    bool pf_act = (tid < 28);
    if (pf_act) { pf_q = tid / 7; pf_u = tid - pf_q*7; pf_act = (pf_u < nj); }
    float a_cur = 0.f;
    if (pf_act)   // step g=1: i=0, l=0
        a_cur = R[((size_t)(pf_q*DIM + j0 + pf_u))*NSAMP + 0];

    #pragma unroll 1
    for (int g = 1; g <= NSTEP; ++g) {
        const int s = g - 1;
        const int i = s >> 2, l = s & 3;

        float a_nxt = 0.f;
        if (pf_act && g < NSTEP) {
            int i2 = g >> 2, l2 = g & 3;
            a_nxt = R[((size_t)(l2*4*DIM + pf_q*DIM + j0 + pf_u))*NSAMP + i2];
        }
        if (tid < 28) ga[(g & 1)*28 + tid] = a_cur;

        // ---- weight prefetch: all 14 uint4 for this step's 7 rows, issued
        //      BEFORE the spin-wait (weights depend only on l, not h)
        uint4 wv0[7], wv1[7];
        #pragma unroll
        for (int t = 0; t < 7; t++) {
            const __half* wr = ws + (((size_t)l*28 + wq*7 + t) << 10);
            wv0[t] = *(const uint4*)&wr[(2*kh    )*256 + lane*8];
            wv1[t] = *(const uint4*)&wr[(2*kh + 1)*256 + lane*8];
        }

        // ---- tagged-quad poll (sticky per-slot freshness)
        {
            const uint4* hb = g_hx + ((s & 1) * NSLOT);
            const unsigned want = (unsigned)s;     // accept tag >= s
            uint4 vv[2];
            unsigned fresh = 0;
            const unsigned all = (1u << nsl) - 1u;
            do {
                #pragma unroll
                for (int k = 0; k < 2; k++) if (k < nsl) {
                    if (!(fresh & (1u << k))) {
                        vv[k] = ldv4(hb + sid2[k]);
                        if (vv[k].w >= want) fresh |= (1u << k);
                    }
                }
            } while (fresh != all);
            #pragma unroll
            for (int k = 0; k < 2; k++) if (k < nsl) {
                unsigned dat[3] = { vv[k].x, vv[k].y, vv[k].z };
                #pragma unroll
                for (int d = 0; d < 3; d++) if (d < dm2[k]) {
                    int j = jb2[k] + d;
                    int p = ((j >> 3) & 3)*256 + (j >> 5)*8 + (j & 7);
                    h_sm[p] = __float2half(__uint_as_float(dat[d]));
                }
            }
        }
        __syncthreads();   // B1

        // ---- load this warp's h half (m8 = 2kh, 2kh+1) as half2
        __half2 hh[8];
        *(uint4*)&hh[0] = *(const uint4*)&h_sm[(2*kh    )*256 + lane*8];
        *(uint4*)&hh[4] = *(const uint4*)&h_sm[(2*kh + 1)*256 + lane*8];

        // ---- 7 rows: HFMA2 on prefetched weights + HADD2-tree flush
        float part[7];
        #pragma unroll
        for (int t = 0; t < 7; t++) {
            const __half2* wa = (const __half2*)&wv0[t];
            const __half2* wb = (const __half2*)&wv1[t];
            __half2 ac0 = __hmul2(wa[0], hh[0]);
            __half2 ac1 = __hmul2(wa[1], hh[1]);
            __half2 ac2 = __hmul2(wa[2], hh[2]);
            __half2 ac3 = __hmul2(wa[3], hh[3]);
            ac0 = __hfma2(wb[0], hh[4], ac0);
            ac1 = __hfma2(wb[1], hh[5], ac1);
            ac2 = __hfma2(wb[2], hh[6], ac2);
            ac3 = __hfma2(wb[3], hh[7], ac3);
            __half2 sall = __hadd2(__hadd2(ac0, ac1), __hadd2(ac2, ac3));
            float2 f = __half22float2(sall);
            part[t] = f.x + f.y;
        }
        #pragma unroll
        for (int t = 0; t < 7; t++) {
            float v = part[t];
            v += __shfl_xor_sync(0xffffffffu, v, 16);
            v += __shfl_xor_sync(0xffffffffu, v, 8);
            v += __shfl_xor_sync(0xffffffffu, v, 4);
            v += __shfl_xor_sync(0xffffffffu, v, 2);
            v += __shfl_xor_sync(0xffffffffu, v, 1);
            if (lane == 0) gpart[kh*28 + wq*7 + t] = v;
        }
        __syncthreads();   // B2

        // ---- gates (hw tanh) + tagged-quad publish (warp 0)
        if (w == 0) {
            float h = 0.f;
            if (lane < nj) {
                const float* gav = ga + (g & 1)*28;
                float gi = gpart[lane]      + gpart[28 + lane]      + gav[lane];
                float gf = gpart[7 + lane]  + gpart[28 + 7 + lane]  + gav[7 + lane];
                float gg = gpart[14 + lane] + gpart[28 + 14 + lane] + gav[14 + lane];
                float go = gpart[21 + lane] + gpart[28 + 21 + lane] + gav[21 + lane];
                float I = sigmoid_hw(gi);
                float F = sigmoid_hw(gf);
                float G = tanh_hw(gg);
                cst = F * cst + I * G;
                float O = sigmoid_hw(go);
                h = O * tanh_hw(cst);
            }
            float p0 = __shfl_sync(0xffffffffu, h, (3*lane)     & 31);
            float p1 = __shfl_sync(0xffffffffu, h, (3*lane + 1) & 31);
            float p2 = __shfl_sync(0xffffffffu, h, (3*lane + 2) & 31);
            if (lane < 3 && 3*lane < nj) {
                uint4 pk;
                pk.x = __float_as_uint(p0);
                pk.y = __float_as_uint(p1);
                pk.z = __float_as_uint(p2);
                pk.w = (unsigned)g;
                stv4(&g_hx[(g & 1)*NSLOT + cta*3 + lane], pk);
            }
            if (lane < nj && l == 3)
                Hbuf[(size_t)i*DIM + j0 + lane] = h;
        }
        a_cur = a_nxt;
        // no trailing barrier: next step's poll self-synchronizes on tags
    }
}

// ---------------------------------------------------------------------------
// Launch
// ---------------------------------------------------------------------------
extern "C" void kernel_launch(void* const* d_in, const int* in_sizes, int n_in,
                              void* d_out, int out_size)
{
    const float* x      = (const float*)d_in[0];
    const int*   ts     = (const int*)  d_in[1];
    const float* proj_w = (const float*)d_in[2];
    const float* proj_b = (const float*)d_in[3];
    const float* te_w1  = (const float*)d_in[4];
    const float* te_b1  = (const float*)d_in[5];
    const float* te_w2  = (const float*)d_in[6];
    const float* te_b2  = (const float*)d_in[7];
    const float* Wih    = (const float*)d_in[8];
    const float* Whh    = (const float*)d_in[9];
    const float* bih    = (const float*)d_in[10];
    const float* bhh    = (const float*)d_in[11];
    const float* lin_w  = (const float*)d_in[12];
    const float* lin_b  = (const float*)d_in[13];
    float* out = (float*)d_out;

    float *R, *H, *BS;
    __half *PEH, *xH, *T1H, *EMBH, *XPH, *tw1H, *tw2H, *pwH, *WihH;
    cudaGetSymbolAddress((void**)&R,    g_R);
    cudaGetSymbolAddress((void**)&H,    g_H);
    cudaGetSymbolAddress((void**)&BS,   g_BS);
    cudaGetSymbolAddress((void**)&PEH,  g_PEH);
    cudaGetSymbolAddress((void**)&xH,   g_xH);
    cudaGetSymbolAddress((void**)&T1H,  g_T1H);
    cudaGetSymbolAddress((void**)&EMBH, g_EMBH);
    cudaGetSymbolAddress((void**)&XPH,  g_XPH);
    cudaGetSymbolAddress((void**)&tw1H, g_tw1H);
    cudaGetSymbolAddress((void**)&tw2H, g_tw2H);
    cudaGetSymbolAddress((void**)&pwH,  g_pwH);
    cudaGetSymbolAddress((void**)&WihH, g_WihH);

    cudaFuncSetAttribute(scan_kernel, cudaFuncAttributeMaxDynamicSharedMemorySize,
                         SCAN_SMEM);

    // 1) sinusoidal PE (fp16 out)
    pe_kernel<<<NSAMP, 128>>>(ts, PEH);
    // 2) fp16 conversions (weights + x + Wih)
    conv_fp16_kernel<<<((DIM*DIM/4)+255)/256, 256>>>(te_w1, tw1H, DIM*DIM/4);
    conv_fp16_kernel<<<((DIM*DIM/4)+255)/256, 256>>>(te_w2, tw2H, DIM*DIM/4);
    conv_fp16_kernel<<<((DIM*DIM/4)+255)/256, 256>>>(proj_w, pwH, DIM*DIM/4);
    conv_fp16_kernel<<<((NSAMP*DIM/4)+255)/256, 256>>>(x, xH, NSAMP*DIM/4);
    conv_fp16_kernel<<<((GROWS*DIM/4)+255)/256, 256>>>(Wih, WihH, GROWS*DIM/4);
    // 3) T1 = silu(PE @ te_w1^T + te_b1)   [HMMA fp16]
    gemm_h16<<<dim3(DIM/64, NSAMP/128), 256>>>(PEH, tw1H, T1H, te_b1, nullptr, 1);
    // 4) EMB = T1 @ te_w2^T + te_b2        [HMMA fp16]
    gemm_h16<<<dim3(DIM/64, NSAMP/128), 256>>>(T1H, tw2H, EMBH, te_b2, nullptr, 0);
    // 5) XP = x @ proj_w^T + proj_b + EMB  [HMMA fp16]
    gemm_h16<<<dim3(DIM/64, NSAMP/128), 256>>>(xH, pwH, XPH, proj_b, EMBH, 0);
    // 6) stacked gate bias
    bias_kernel<<<GROWS/256, 256>>>(bih, bhh, BS);
    // 7) R = Wih_stack @ XP^T + bias   (16384 x 4096 x 1024) — fp16 HMMA
    gemm_r_fp16<<<dim3(NSAMP/64, GROWS/128), 256>>>(WihH, XPH, BS, R);
    // 8) reset tagged h slots (graph-replay safe)
    reset_kernel<<<(2*NSLOT+255)/256, 256>>>();
    // 9) persistent sequential scan
    scan_kernel<<<SCAN_CTAS, SCAN_TPB, SCAN_SMEM>>>(Whh, R, H);
    // 10) out = H @ lin_w^T + lin_b (fp32 — output precision)
    gemm_nt<<<dim3(DIM/128, NSAMP/128), 256>>>(H, lin_w, out, NSAMP, DIM, DIM,
                                               nullptr, lin_b, nullptr, 0);
}